// round 6
// baseline (speedup 1.0000x reference)
#include <cuda_runtime.h>
#include <math.h>

#define Qn 1024
#define Tn 256
#define Nn 100
#define Kn 300      // 3*N flattened reduction dim
#define PITCH 306   // pred tile pitch: even (8B align), 306%32=18
#define QB 32       // q tile per block
#define QTT 8       // q per thread

typedef unsigned long long u64;

__device__ float g_cls[Qn * 8];   // [0..3]=log(type_prob+eps), [4]=log(valid0+eps), [5..6]=log(closed+eps), [7]=p2
__device__ float g_v2[Tn];
__device__ int   g_lab[Tn];
__device__ int   g_clo[Tn];
__device__ int   g_tperm[Tn];     // closed t's first, open t's last

// packed fp32x2 FMA: c = a*b + c  -> SASS FFMA2
__device__ __forceinline__ void ffma2(u64& c, u64 a, u64 b) {
    asm("fma.rn.f32x2 %0, %1, %2, %3;" : "=l"(c) : "l"(a), "l"(b), "l"(c));
}
__device__ __forceinline__ u64 pack2(float x, float y) {
    u64 r;
    asm("mov.b64 %0, {%1, %2};" : "=l"(r) : "f"(x), "f"(y));
    return r;
}
__device__ __forceinline__ float pairsum(u64 v) {
    return __uint_as_float((unsigned)v) + __uint_as_float((unsigned)(v >> 32));
}

// ---------------------------------------------------------------------------
__global__ void pre_kernel(const float* __restrict__ pred,
                           const float* __restrict__ vlog,
                           const float* __restrict__ tlog,
                           const float* __restrict__ clog,
                           const float* __restrict__ tgt,
                           const int* __restrict__ lab32,
                           const int* __restrict__ clo32)
{
    const int tid = threadIdx.x;
    if (blockIdx.x < 4) {
        const int q = blockIdx.x * 256 + tid;
        float x0 = tlog[q*4+0], x1 = tlog[q*4+1], x2 = tlog[q*4+2], x3 = tlog[q*4+3];
        float m  = fmaxf(fmaxf(x0, x1), fmaxf(x2, x3));
        float e0 = expf(x0-m), e1 = expf(x1-m), e2 = expf(x2-m), e3 = expf(x3-m);
        float s  = e0 + e1 + e2 + e3;
        g_cls[q*8+0] = logf(e0/s + 1e-6f);
        g_cls[q*8+1] = logf(e1/s + 1e-6f);
        g_cls[q*8+2] = logf(e2/s + 1e-6f);
        g_cls[q*8+3] = logf(e3/s + 1e-6f);
        float a0 = vlog[q*2+0], a1 = vlog[q*2+1];
        float ma = fmaxf(a0, a1);
        float f0 = expf(a0-ma), f1 = expf(a1-ma);
        g_cls[q*8+4] = logf(f0/(f0+f1) + 1e-6f);
        float b0 = clog[q*2+0], b1 = clog[q*2+1];
        float mb = fmaxf(b0, b1);
        float h0 = expf(b0-mb), h1 = expf(b1-mb);
        float hs = h0 + h1;
        g_cls[q*8+5] = logf(h0/hs + 1e-6f);
        g_cls[q*8+6] = logf(h1/hs + 1e-6f);
        float p2 = 0.f;
        for (int k = 0; k < Kn; k++) { float v = pred[q*Kn+k]; p2 = fmaf(v, v, p2); }
        g_cls[q*8+7] = p2;
    } else {
        // dtype detection: int64 data read as int32 has all odd words == 0
        __shared__ int flag;
        if (tid == 0) flag = 0;
        __syncthreads();
        if (tid < 128) {
            if (lab32[2*tid+1] != 0 || clo32[2*tid+1] != 0) atomicOr(&flag, 1);
        }
        __syncthreads();
        const int t = tid;
        int lv, cv;
        if (flag) { lv = lab32[t]; cv = clo32[t]; }
        else {
            lv = (int)((const long long*)lab32)[t];
            cv = (int)((const long long*)clo32)[t];
        }
        g_lab[t] = lv;
        g_clo[t] = cv;
        float v2 = 0.f;
        for (int k = 0; k < Kn; k++) { float v = tgt[t*Kn+k]; v2 = fmaf(v, v, v2); }
        g_v2[t] = v2;
        __syncthreads();
        if (tid == 0) {
            int a = 0, b = 0;
            for (int i = 0; i < Tn; i++) if (g_clo[i]) g_tperm[a++] = i;
            for (int i = 0; i < Tn; i++) if (!g_clo[i]) g_tperm[a + (b++)] = i;
        }
    }
}

// extended (circular) target value: idx in [0, 600)
__device__ __forceinline__ float sext_fwd(const float* __restrict__ tg, int idx) {
    int m = idx / 3, c = idx - m * 3;
    int mm = (m >= Nn) ? (m - Nn) : m;
    return tg[mm * 3 + c];
}
__device__ __forceinline__ float sext_bwd(const float* __restrict__ tg, int idx) {
    int m = idx / 3, c = idx - m * 3;
    int mm = (m >= Nn) ? (m - Nn) : m;
    return tg[(Nn - 1 - mm) * 3 + c];
}

// ---------------------------------------------------------------------------
__device__ __forceinline__ void epilogue_write(
    float best_ab, int ids, int t, int q, int clos,
    const float* __restrict__ clw, float* __restrict__ out, int write_ids)
{
    const float p2 = g_cls[q*8+7];
    float d2 = fmaxf(g_v2[t] + p2 - 2.0f * best_ab, 0.0f) / 100.0f;
    const int lab = g_lab[t];
    float cls = g_cls[q*8+lab] + g_cls[q*8+4] + g_cls[q*8+5+clos];
    float C = d2 * clw[t] - cls;
    out[q * Tn + t] = C;
    if (write_ids) out[Qn * Tn + q * Tn + t] = (float)ids;
}

__global__ void __launch_bounds__(128, 3)
match_kernel(const float* __restrict__ pred, const float* __restrict__ tgt,
             const float* __restrict__ clw, float* __restrict__ out, int write_ids)
{
    extern __shared__ float sm[];
    float*  predsh = sm;                       // QB * PITCH floats
    float4* sp4f   = (float4*)(sm + QB * PITCH);   // 600 float4: (sext[j..j+3]) fwd
    float4* sp4b   = sp4f + 600;               // 600 float4: bwd
    float*  redv   = (float*)(sp4b + 600);     // 64
    int*    redi   = (int*)(redv + 64);        // 64

    const int t   = g_tperm[blockIdx.x];
    const int q0  = blockIdx.y * QB;
    const int tid = threadIdx.x;
    const float* tg = tgt + t * Kn;
    const int clos = g_clo[t];

    if (clos) {
        // stage pred tile: coalesced global read, conflict-free shared write
        for (int idx = tid; idx < QB * Kn; idx += 128) {
            int q = idx / Kn;
            int k = idx - q * Kn;
            predsh[q * PITCH + k] = pred[q0 * Kn + idx];
        }
        for (int j = tid; j < 600; j += 128) {
            float f0 = sext_fwd(tg, j);
            float f1 = (j < 599) ? sext_fwd(tg, j + 1) : 0.f;
            float f2 = (j < 598) ? sext_fwd(tg, j + 2) : 0.f;
            float f3 = (j < 597) ? sext_fwd(tg, j + 3) : 0.f;
            sp4f[j] = make_float4(f0, f1, f2, f3);
            float b0 = sext_bwd(tg, j);
            float b1 = (j < 599) ? sext_bwd(tg, j + 1) : 0.f;
            float b2 = (j < 598) ? sext_bwd(tg, j + 2) : 0.f;
            float b3 = (j < 597) ? sext_bwd(tg, j + 3) : 0.f;
            sp4b[j] = make_float4(b0, b1, b2, b3);
        }
    } else {
        // light path only reads .xy at even j in [300, 600)
        for (int j = 300 + tid; j < 600; j += 128) {
            float f0 = sext_fwd(tg, j);
            float f1 = (j < 599) ? sext_fwd(tg, j + 1) : 0.f;
            sp4f[j] = make_float4(f0, f1, 0.f, 0.f);
            float b0 = sext_bwd(tg, j);
            float b1 = (j < 599) ? sext_bwd(tg, j + 1) : 0.f;
            sp4b[j] = make_float4(b0, b1, 0.f, 0.f);
        }
    }
    __syncthreads();

    if (clos) {
        // ---- heavy path: 4 warps = dir(2) x wq(2), packed f32x2 FMA along k ----
        const int lane  = tid & 31;
        const int w     = tid >> 5;
        const int vlane = lane & 15;
        const int qlane = lane >> 4;
        const int wq    = w & 1;
        const int dir   = w >> 1;      // 0 = fwd, 1 = bwd
        const float4* sp4 = dir ? sp4b : sp4f;
        const int qb = wq * 16 + qlane * QTT;
        const float* pb = predsh + qb * PITCH;

        u64 acc[7][QTT];
        #pragma unroll
        for (int i = 0; i < 7; i++)
            #pragma unroll
            for (int u = 0; u < QTT; u++) acc[i][u] = 0ull;

        int off[7];
        #pragma unroll
        for (int i = 0; i < 7; i++) {
            int v = vlane + 16 * i;
            if (v > 99) v = 99;            // clamped duplicates: harmless for max
            off[i] = (100 - v) * 3;
        }

        #pragma unroll 1
        for (int k = 0; k < Kn; k += 4) {
            // one LDS.128 per variant group covers two k-pairs
            float4 s4[7];
            #pragma unroll
            for (int i = 0; i < 7; i++)
                s4[i] = sp4[k + off[i]];
            // first k-pair
            {
                u64 p[QTT];
                #pragma unroll
                for (int u = 0; u < QTT; u++)
                    p[u] = *(const u64*)(pb + u * PITCH + k);
                #pragma unroll
                for (int i = 0; i < 7; i++) {
                    u64 s01 = pack2(s4[i].x, s4[i].y);
                    #pragma unroll
                    for (int u = 0; u < QTT; u++)
                        ffma2(acc[i][u], p[u], s01);
                }
            }
            // second k-pair
            {
                u64 p[QTT];
                #pragma unroll
                for (int u = 0; u < QTT; u++)
                    p[u] = *(const u64*)(pb + u * PITCH + k + 2);
                #pragma unroll
                for (int i = 0; i < 7; i++) {
                    u64 s23 = pack2(s4[i].z, s4[i].w);
                    #pragma unroll
                    for (int u = 0; u < QTT; u++)
                        ffma2(acc[i][u], p[u], s23);
                }
            }
        }

        // per-q max(ab) with first-index tie-break, reduce across 16 v-lanes
        #pragma unroll
        for (int u = 0; u < QTT; u++) {
            float bv = pairsum(acc[0][u]);
            int   bx = vlane;
            #pragma unroll
            for (int i = 1; i < 7; i++) {
                int v = vlane + 16 * i;
                if (v > 99) v = 99;
                float av = pairsum(acc[i][u]);
                if (av > bv) { bv = av; bx = v; }   // strict >: keeps smaller v on tie
            }
            #pragma unroll
            for (int m = 8; m >= 1; m >>= 1) {
                float ov = __shfl_xor_sync(0xffffffffu, bv, m);
                int   ox = __shfl_xor_sync(0xffffffffu, bx, m);
                if (ov > bv || (ov == bv && ox < bx)) { bv = ov; bx = ox; }
            }
            if (vlane == 0) {
                redv[dir * QB + qb + u] = bv;
                redi[dir * QB + qb + u] = bx;
            }
        }
        __syncthreads();

        if (tid < QB) {
            float bf = redv[tid];      int xf = redi[tid];
            float bw = redv[QB + tid]; int xb = redi[QB + tid];
            float best; int ids;
            if (bw > bf) { best = bw; ids = 99 - xb; }  // bwd raw idx = 100+xb -> 2n-1-idx
            else         { best = bf; ids = xf; }       // tie -> fwd (smaller raw index)
            epilogue_write(best, ids, t, q0 + tid, clos, clw, out, write_ids);
        }
    } else {
        // ---- light path: open curve, variants v=0 (fwd) and v=n (bwd) only ----
        if (tid < QB) {
            const u64* pq = (const u64*)(pred + (q0 + tid) * Kn);
            u64 af = 0ull, ab = 0ull;
            #pragma unroll 2
            for (int k2 = 0; k2 < Kn / 2; k2++) {
                u64 p = pq[k2];
                const float4 sf4 = sp4f[2 * k2 + 300];
                const float4 sb4 = sp4b[2 * k2 + 300];
                ffma2(af, p, pack2(sf4.x, sf4.y));
                ffma2(ab, p, pack2(sb4.x, sb4.y));
            }
            float best = fmaxf(pairsum(af), pairsum(ab));
            epilogue_write(best, 0, t, q0 + tid, clos, clw, out, write_ids);
        }
    }
}

// ---------------------------------------------------------------------------
extern "C" void kernel_launch(void* const* d_in, const int* in_sizes, int n_in,
                              void* d_out, int out_size)
{
    const float* pred = (const float*)d_in[0];   // pred_curve_points (1,Q,N,3)
    const float* vlog = (const float*)d_in[1];   // pred_curve_logits (1,Q,2)
    const float* tlog = (const float*)d_in[2];   // pred_curve_type   (1,Q,4)
    const float* clog = (const float*)d_in[3];   // closed_curve_logits (1,Q,2)
    const float* tgt  = (const float*)d_in[4];   // tgt_curve_points (T,N,3)
    const int*   lab  = (const int*)d_in[5];     // tgt_labels (int32 or int64)
    const int*   clo  = (const int*)d_in[6];     // tgt_is_closed
    const float* clw  = (const float*)d_in[7];   // curve_length_weighting (T)
    float* out = (float*)d_out;

    const int smem = (QB * PITCH) * (int)sizeof(float) + 1200 * (int)sizeof(float4)
                   + 64 * (int)sizeof(float) + 64 * (int)sizeof(int);
    cudaFuncSetAttribute(match_kernel, cudaFuncAttributeMaxDynamicSharedMemorySize, smem);

    const int write_ids = (out_size >= 2 * Qn * Tn) ? 1 : 0;

    pre_kernel<<<5, 256>>>(pred, vlog, tlog, clog, tgt, lab, clo);
    match_kernel<<<dim3(Tn, Qn / QB), 128, smem>>>(pred, tgt, clw, out, write_ids);
}

// round 9
// speedup vs baseline: 1.5548x; 1.5548x over previous
#include <cuda_runtime.h>
#include <cuda_bf16.h>
#include <math.h>

#define Qn 1024
#define Tn 256
#define Nn 100
#define Kn 300
#define KP 320          // padded K (5 chunks of 64)
#define EPSGAP 0.02f    // bf16-path ambiguity threshold for exact rescue

typedef unsigned long long u64;

__device__ float g_cls[Qn * 8];
__device__ float g_v2[Tn];
__device__ int   g_lab[Tn];
__device__ int   g_clo[Tn];
__device__ int   g_tperm[Tn];
__device__ __nv_bfloat16 g_pb_hi[Qn * KP];   // pred bf16 hi plane, [q][KP]
__device__ __nv_bfloat16 g_pb_lo[Qn * KP];   // residual plane
__device__ unsigned g_sp_hi[2 * Tn * 648];   // extended-target pair table (bf16x2), hi
__device__ unsigned g_sp_lo[2 * Tn * 648];   // lo
__device__ float g_pab[2 * Tn * Qn];         // per-(dir,t,q) best ab
__device__ int   g_pix[2 * Tn * Qn];         // its v index
__device__ float g_pv2[2 * Tn * Qn];         // runner-up ab
__device__ int   g_flist[Tn * Qn];           // flagged (t<<10|q)
__device__ int   g_fcnt;

__device__ __forceinline__ void ffma2(u64& c, u64 a, u64 b) {
    asm("fma.rn.f32x2 %0, %1, %2, %3;" : "=l"(c) : "l"(a), "l"(b), "l"(c));
}
__device__ __forceinline__ float pairsum(u64 v) {
    return __uint_as_float((unsigned)v) + __uint_as_float((unsigned)(v >> 32));
}
__device__ __forceinline__ void mma16816(float* c, const unsigned* a, unsigned b0, unsigned b1) {
    asm volatile(
        "mma.sync.aligned.m16n8k16.row.col.f32.bf16.bf16.f32 "
        "{%0,%1,%2,%3}, {%4,%5,%6,%7}, {%8,%9}, {%0,%1,%2,%3};"
        : "+f"(c[0]), "+f"(c[1]), "+f"(c[2]), "+f"(c[3])
        : "r"(a[0]), "r"(a[1]), "r"(a[2]), "r"(a[3]), "r"(b0), "r"(b1));
}
// top-2 merge: (v1,x1,v2) <- merge with (ov1,ox1,ov2); equal top values => v2 = v1 (gap 0)
__device__ __forceinline__ void top2_merge(float& v1, int& x1, float& v2,
                                           float ov1, int ox1, float ov2) {
    float lo = fminf(v1, ov1);
    if (ov1 > v1)               { v1 = ov1; x1 = ox1; }
    else if (ov1 == v1 && ox1 < x1) x1 = ox1;
    v2 = fmaxf(v2, fmaxf(lo, ov2));
}

// ---------------------------------------------------------------------------
__device__ __forceinline__ float sext_fwd(const float* __restrict__ tg, int idx) {
    int m = idx / 3, c = idx - m * 3;
    int mm = (m >= Nn) ? (m - Nn) : m;
    return tg[mm * 3 + c];
}
__device__ __forceinline__ float sext_bwd(const float* __restrict__ tg, int idx) {
    int m = idx / 3, c = idx - m * 3;
    int mm = (m >= Nn) ? (m - Nn) : m;
    return tg[(Nn - 1 - mm) * 3 + c];
}

// ---------------------------------------------------------------------------
__global__ void pre_kernel(const float* __restrict__ pred,
                           const float* __restrict__ vlog,
                           const float* __restrict__ tlog,
                           const float* __restrict__ clog,
                           const float* __restrict__ tgt,
                           const int* __restrict__ lab32,
                           const int* __restrict__ clo32)
{
    const int tid = threadIdx.x;
    if (blockIdx.x < 4) {
        const int q = blockIdx.x * 256 + tid;
        float x0 = tlog[q*4+0], x1 = tlog[q*4+1], x2 = tlog[q*4+2], x3 = tlog[q*4+3];
        float m  = fmaxf(fmaxf(x0, x1), fmaxf(x2, x3));
        float e0 = expf(x0-m), e1 = expf(x1-m), e2 = expf(x2-m), e3 = expf(x3-m);
        float s  = e0 + e1 + e2 + e3;
        g_cls[q*8+0] = logf(e0/s + 1e-6f);
        g_cls[q*8+1] = logf(e1/s + 1e-6f);
        g_cls[q*8+2] = logf(e2/s + 1e-6f);
        g_cls[q*8+3] = logf(e3/s + 1e-6f);
        float a0 = vlog[q*2+0], a1 = vlog[q*2+1];
        float ma = fmaxf(a0, a1);
        float f0 = expf(a0-ma), f1 = expf(a1-ma);
        g_cls[q*8+4] = logf(f0/(f0+f1) + 1e-6f);
        float b0 = clog[q*2+0], b1 = clog[q*2+1];
        float mb = fmaxf(b0, b1);
        float h0 = expf(b0-mb), h1 = expf(b1-mb);
        float hs = h0 + h1;
        g_cls[q*8+5] = logf(h0/hs + 1e-6f);
        g_cls[q*8+6] = logf(h1/hs + 1e-6f);
        float p2 = 0.f;
        for (int k = 0; k < Kn; k++) { float v = pred[q*Kn+k]; p2 = fmaf(v, v, p2); }
        g_cls[q*8+7] = p2;
    } else {
        if (tid == 0) g_fcnt = 0;   // reset rescue list every launch (graph replays)
        __shared__ int flag;
        if (tid == 0) flag = 0;
        __syncthreads();
        if (tid < 128) {
            if (lab32[2*tid+1] != 0 || clo32[2*tid+1] != 0) atomicOr(&flag, 1);
        }
        __syncthreads();
        const int t = tid;
        int lv, cv;
        if (flag) { lv = lab32[t]; cv = clo32[t]; }
        else {
            lv = (int)((const long long*)lab32)[t];
            cv = (int)((const long long*)clo32)[t];
        }
        g_lab[t] = lv;
        g_clo[t] = cv;
        float v2 = 0.f;
        for (int k = 0; k < Kn; k++) { float v = tgt[t*Kn+k]; v2 = fmaf(v, v, v2); }
        g_v2[t] = v2;
        __syncthreads();
        if (tid == 0) {
            int a = 0, b = 0;
            for (int i = 0; i < Tn; i++) if (g_clo[i]) g_tperm[a++] = i;
            for (int i = 0; i < Tn; i++) if (!g_clo[i]) g_tperm[a + (b++)] = i;
        }
    }
}

// bf16 hi/lo planes for preds (K-major, zero-padded) and target pair tables
__global__ void pre2_kernel(const float* __restrict__ pred,
                            const float* __restrict__ tgt)
{
    int idx = blockIdx.x * 256 + threadIdx.x;
    if (blockIdx.x < 1280) {
        int q = idx / KP, k = idx - q * KP;
        float x = (k < Kn) ? pred[q * Kn + k] : 0.f;
        __nv_bfloat16 hi = __float2bfloat16(x);
        g_pb_hi[idx] = hi;
        g_pb_lo[idx] = __float2bfloat16(x - __bfloat162float(hi));
    } else {
        int i2 = idx - 1280 * 256;
        if (i2 >= 2 * Tn * 648) return;
        int dt = i2 / 648, j = i2 - dt * 648;
        int dir = dt >> 8, t = dt & 255;
        const float* tg = tgt + t * Kn;
        float x0 = 0.f, x1 = 0.f;
        if (j < 600)     x0 = dir ? sext_bwd(tg, j)     : sext_fwd(tg, j);
        if (j + 1 < 600) x1 = dir ? sext_bwd(tg, j + 1) : sext_fwd(tg, j + 1);
        __nv_bfloat16 h0 = __float2bfloat16(x0), h1 = __float2bfloat16(x1);
        __nv_bfloat16 l0 = __float2bfloat16(x0 - __bfloat162float(h0));
        __nv_bfloat16 l1 = __float2bfloat16(x1 - __bfloat162float(h1));
        g_sp_hi[i2] = (unsigned)__bfloat16_as_ushort(h0) | ((unsigned)__bfloat16_as_ushort(h1) << 16);
        g_sp_lo[i2] = (unsigned)__bfloat16_as_ushort(l0) | ((unsigned)__bfloat16_as_ushort(l1) << 16);
    }
}

// ---------------------------------------------------------------------------
__device__ __forceinline__ void epilogue_write(
    float best_ab, int ids, int t, int q, int clos,
    const float* __restrict__ clw, float* __restrict__ out, int write_ids)
{
    const float p2 = g_cls[q*8+7];
    float d2 = fmaxf(g_v2[t] + p2 - 2.0f * best_ab, 0.0f) / 100.0f;
    const int lab = g_lab[t];
    float cls = g_cls[q*8+lab] + g_cls[q*8+4] + g_cls[q*8+5+clos];
    float C = d2 * clw[t] - cls;
    out[q * Tn + t] = C;
    if (write_ids) out[Qn * Tn + q * Tn + t] = (float)ids;
}

// ---------------------------------------------------------------------------
// HMMA kernel: one CTA = (closed t, dir, 128-q tile). 8 warps = 4(M) x 2(N).
#define BPITCH 144
__global__ void __launch_bounds__(256, 2)
mma_kernel(int write_ids)
{
    __shared__ unsigned ssph[648], sspl[648];
    __shared__ char sB[2][128 * BPITCH];
    __shared__ float redv[4][128];
    __shared__ int   redi[4][128];
    __shared__ float redv2[4][128];

    const int tid  = threadIdx.x;
    const int wid  = tid >> 5, lane = tid & 31;
    const int wm   = wid & 3,  wn = wid >> 2;
    const int t    = g_tperm[blockIdx.x];
    if (!g_clo[t]) return;
    const int dir  = blockIdx.y >> 3;
    const int q0   = (blockIdx.y & 7) * 128;
    const int m0   = wm * 32;
    const int n0   = wn * 64;
    const int g    = lane >> 2;
    const int t2   = (lane & 3) * 2;

    {
        const unsigned* gh = g_sp_hi + (dir * Tn + t) * 648;
        const unsigned* gl = g_sp_lo + (dir * Tn + t) * 648;
        for (int j = tid; j < 648; j += 256) { ssph[j] = gh[j]; sspl[j] = gl[j]; }
    }

    float c[2][8][4];
    #pragma unroll
    for (int mt = 0; mt < 2; mt++)
        #pragma unroll
        for (int nt = 0; nt < 8; nt++)
            #pragma unroll
            for (int r = 0; r < 4; r++) c[mt][nt][r] = 0.f;

    int off0[2], off1[2];
    bool val0[2], val1[2];
    #pragma unroll
    for (int mt = 0; mt < 2; mt++) {
        int v0 = m0 + mt * 16 + g;
        val0[mt] = (v0 < 100);
        val1[mt] = (v0 + 8 < 100);
        off0[mt] = val0[mt] ? 3 * (100 - v0) : 0;       // clamped: no OOB smem addr
        off1[mt] = val1[mt] ? 3 * (100 - v0) - 24 : 0;
    }

    for (int kc = 0; kc < 5; kc++) {
        __syncthreads();
        #pragma unroll
        for (int plane = 0; plane < 2; plane++) {
            const __nv_bfloat16* src = (plane ? g_pb_lo : g_pb_hi);
            for (int i = tid; i < 128 * 16; i += 256) {
                int row = i >> 4, w = i & 15;
                u64 v = *(const u64*)(src + (u64)(q0 + row) * KP + kc * 64 + w * 4);
                *(u64*)(sB[plane] + row * BPITCH + w * 8) = v;
            }
        }
        __syncthreads();

        #pragma unroll
        for (int ks = 0; ks < 4; ks++) {
            const int kk = kc * 64 + ks * 16 + t2;
            unsigned ah[2][4], al[2][4];
            #pragma unroll
            for (int mt = 0; mt < 2; mt++) {
                ah[mt][0] = val0[mt] ? ssph[off0[mt] + kk]     : 0u;
                ah[mt][1] = val1[mt] ? ssph[off1[mt] + kk]     : 0u;
                ah[mt][2] = val0[mt] ? ssph[off0[mt] + kk + 8] : 0u;
                ah[mt][3] = val1[mt] ? ssph[off1[mt] + kk + 8] : 0u;
                al[mt][0] = val0[mt] ? sspl[off0[mt] + kk]     : 0u;
                al[mt][1] = val1[mt] ? sspl[off1[mt] + kk]     : 0u;
                al[mt][2] = val0[mt] ? sspl[off0[mt] + kk + 8] : 0u;
                al[mt][3] = val1[mt] ? sspl[off1[mt] + kk + 8] : 0u;
            }
            #pragma unroll
            for (int nt = 0; nt < 8; nt++) {
                const int brow = n0 + nt * 8 + g;
                const char* bh = sB[0] + brow * BPITCH + (ks * 16 + t2) * 2;
                const char* bl = sB[1] + brow * BPITCH + (ks * 16 + t2) * 2;
                unsigned bh0 = *(const unsigned*)bh;
                unsigned bh1 = *(const unsigned*)(bh + 16);
                unsigned bl0 = *(const unsigned*)bl;
                unsigned bl1 = *(const unsigned*)(bl + 16);
                #pragma unroll
                for (int mt = 0; mt < 2; mt++) {
                    mma16816(c[mt][nt], ah[mt], bh0, bh1);
                    mma16816(c[mt][nt], al[mt], bh0, bh1);
                    mma16816(c[mt][nt], ah[mt], bl0, bl1);
                }
            }
        }
    }

    // ---- epilogue: top-2 argmax over v per q column ----
    const float NINF = -__int_as_float(0x7f800000);
    #pragma unroll
    for (int nt = 0; nt < 8; nt++) {
        #pragma unroll
        for (int cp = 0; cp < 2; cp++) {
            float bv = NINF; int bx = 127; float bv2 = NINF;
            #pragma unroll
            for (int mt = 0; mt < 2; mt++) {
                #pragma unroll
                for (int rh = 0; rh < 2; rh++) {
                    int v = m0 + mt * 16 + rh * 8 + g;
                    float val = (v < 100) ? c[mt][nt][rh * 2 + cp] : NINF;
                    top2_merge(bv, bx, bv2, val, v, NINF);
                }
            }
            #pragma unroll
            for (int m = 4; m <= 16; m <<= 1) {
                float ov  = __shfl_xor_sync(0xffffffffu, bv, m);
                int   ox  = __shfl_xor_sync(0xffffffffu, bx, m);
                float ov2 = __shfl_xor_sync(0xffffffffu, bv2, m);
                top2_merge(bv, bx, bv2, ov, ox, ov2);
            }
            if (lane < 4) {
                int col = n0 + nt * 8 + t2 + cp;
                redv[wm][col]  = bv;
                redi[wm][col]  = bx;
                redv2[wm][col] = bv2;
            }
        }
    }
    __syncthreads();
    if (tid < 128) {
        int col = tid;
        float bv = redv[0][col]; int bx = redi[0][col]; float bv2 = redv2[0][col];
        #pragma unroll
        for (int w = 1; w < 4; w++)
            top2_merge(bv, bx, bv2, redv[w][col], redi[w][col], redv2[w][col]);
        int o = (dir * Tn + t) * Qn + q0 + col;
        g_pab[o] = bv; g_pix[o] = bx; g_pv2[o] = bv2;
    }
}

// ---------------------------------------------------------------------------
__global__ void combine_kernel(const float* __restrict__ clw,
                               float* __restrict__ out, int write_ids)
{
    int idx = blockIdx.x * 256 + threadIdx.x;
    int t = idx >> 10, q = idx & 1023;
    if (!g_clo[t]) return;
    float f1 = g_pab[t * Qn + q];        int xf = g_pix[t * Qn + q];
    float f2 = g_pv2[t * Qn + q];
    float w1 = g_pab[(Tn + t) * Qn + q]; int xb = g_pix[(Tn + t) * Qn + q];
    float w2 = g_pv2[(Tn + t) * Qn + q];
    float best, second; int ids;
    if (w1 > f1) { best = w1; ids = 99 - xb; second = fmaxf(f1, w2); }
    else         { best = f1; ids = xf;      second = fmaxf(w1, f2); }
    epilogue_write(best, ids, t, q, 1, clw, out, write_ids);
    if (best - second < EPSGAP) {
        int slot = atomicAdd(&g_fcnt, 1);
        g_flist[slot] = (t << 10) | q;
    }
}

// ---------------------------------------------------------------------------
// exact fp32 rescue: one warp per ambiguous (t,q), all 200 variants
__global__ void __launch_bounds__(256)
rescue_kernel(const float* __restrict__ pred, const float* __restrict__ tgt,
              const float* __restrict__ clw, float* __restrict__ out, int write_ids)
{
    const int lane = threadIdx.x & 31;
    const int gw   = (blockIdx.x * 256 + threadIdx.x) >> 5;
    const int nw   = gridDim.x * 8;
    const int n    = g_fcnt;
    const float NINF = -__int_as_float(0x7f800000);
    for (int i = gw; i < n; i += nw) {
        int code = g_flist[i];
        int t = code >> 10, q = code & 1023;
        const float* tg = tgt + t * Kn;
        const float* pq = pred + q * Kn;
        float bv = NINF; int bx = 255;
        for (int r = lane; r < 200; r += 32) {      // ascending raw idx per lane
            int  sh  = (r < 100) ? (100 - r) : (200 - r);
            bool rev = (r >= 100);
            float c0 = 0.f, c1 = 0.f, c2 = 0.f;
            for (int j = 0; j < 100; j++) {
                int jj = j + sh; if (jj >= 100) jj -= 100;
                int row = rev ? (99 - jj) : jj;
                c0 = fmaf(pq[j*3+0], tg[row*3+0], c0);
                c1 = fmaf(pq[j*3+1], tg[row*3+1], c1);
                c2 = fmaf(pq[j*3+2], tg[row*3+2], c2);
            }
            float ab = c0 + c1 + c2;
            if (ab > bv) { bv = ab; bx = r; }       // strict >: smallest raw on tie
        }
        #pragma unroll
        for (int m = 16; m >= 1; m >>= 1) {
            float ov = __shfl_xor_sync(0xffffffffu, bv, m);
            int   ox = __shfl_xor_sync(0xffffffffu, bx, m);
            if (ov > bv || (ov == bv && ox < bx)) { bv = ov; bx = ox; }
        }
        if (lane == 0) {
            int ids = (bx < 100) ? bx : 199 - bx;
            epilogue_write(bv, ids, t, q, 1, clw, out, write_ids);
        }
    }
}

// ---------------------------------------------------------------------------
// open curves: only variants v=0 (fwd) and v=n (bwd), full fp32
__global__ void __launch_bounds__(256)
light_kernel(const float* __restrict__ pred, const float* __restrict__ tgt,
             const float* __restrict__ clw, float* __restrict__ out, int write_ids)
{
    __shared__ float2 pf[152], pb2[152];
    const int t = blockIdx.x;
    if (g_clo[t]) return;
    const int q = blockIdx.y * 256 + threadIdx.x;
    const float* tg = tgt + t * Kn;
    for (int i = threadIdx.x; i < 150; i += 256) {
        int j = 300 + 2 * i;
        pf[i]  = make_float2(sext_fwd(tg, j), sext_fwd(tg, j + 1));
        pb2[i] = make_float2(sext_bwd(tg, j), sext_bwd(tg, j + 1));
    }
    __syncthreads();
    const u64* pq = (const u64*)(pred + q * Kn);
    u64 af = 0ull, ab = 0ull;
    #pragma unroll 2
    for (int i = 0; i < 150; i++) {
        u64 p = pq[i];
        ffma2(af, p, ((const u64*)pf)[i]);
        ffma2(ab, p, ((const u64*)pb2)[i]);
    }
    epilogue_write(fmaxf(pairsum(af), pairsum(ab)), 0, t, q, 0, clw, out, write_ids);
}

// ---------------------------------------------------------------------------
extern "C" void kernel_launch(void* const* d_in, const int* in_sizes, int n_in,
                              void* d_out, int out_size)
{
    const float* pred = (const float*)d_in[0];
    const float* vlog = (const float*)d_in[1];
    const float* tlog = (const float*)d_in[2];
    const float* clog = (const float*)d_in[3];
    const float* tgt  = (const float*)d_in[4];
    const int*   lab  = (const int*)d_in[5];
    const int*   clo  = (const int*)d_in[6];
    const float* clw  = (const float*)d_in[7];
    float* out = (float*)d_out;

    const int write_ids = (out_size >= 2 * Qn * Tn) ? 1 : 0;

    pre_kernel<<<5, 256>>>(pred, vlog, tlog, clog, tgt, lab, clo);
    pre2_kernel<<<1280 + 1296, 256>>>(pred, tgt);
    mma_kernel<<<dim3(Tn, 16), 256>>>(write_ids);
    light_kernel<<<dim3(Tn, 4), 256>>>(pred, tgt, clw, out, write_ids);
    combine_kernel<<<1024, 256>>>(clw, out, write_ids);
    rescue_kernel<<<512, 256>>>(pred, tgt, clw, out, write_ids);
}

// round 10
// speedup vs baseline: 1.7681x; 1.1372x over previous
#include <cuda_runtime.h>
#include <cuda_bf16.h>
#include <math.h>

#define Qn 1024
#define Tn 256
#define Nn 100
#define Kn 300
#define KP 320          // padded K (5 chunks of 64)
#define EPSGAP 0.02f    // bf16-path ambiguity threshold for exact rescue

typedef unsigned long long u64;

__device__ float g_cls[Qn * 8];
__device__ float g_v2[Tn];
__device__ int   g_lab[Tn];
__device__ int   g_clo[Tn];
__device__ int   g_tperm[Tn];
__device__ __nv_bfloat16 g_pb_hi[Qn * KP];   // pred bf16 hi plane, [q][KP]
__device__ __nv_bfloat16 g_pb_lo[Qn * KP];   // residual plane
__device__ unsigned g_sp_hi[2 * Tn * 648];   // extended-target pair table (bf16x2), hi
__device__ unsigned g_sp_lo[2 * Tn * 648];   // lo
__device__ float g_pab[2 * Tn * Qn];         // per-(dir,t,q) best ab
__device__ int   g_pix[2 * Tn * Qn];         // its v index
__device__ float g_pv2[2 * Tn * Qn];         // runner-up ab
__device__ int   g_flist[Tn * Qn];           // flagged (t<<10|q)
__device__ int   g_fcnt;

__device__ __forceinline__ void ffma2(u64& c, u64 a, u64 b) {
    asm("fma.rn.f32x2 %0, %1, %2, %3;" : "=l"(c) : "l"(a), "l"(b), "l"(c));
}
__device__ __forceinline__ float pairsum(u64 v) {
    return __uint_as_float((unsigned)v) + __uint_as_float((unsigned)(v >> 32));
}
__device__ __forceinline__ void mma16816(float* c, const unsigned* a, unsigned b0, unsigned b1) {
    asm volatile(
        "mma.sync.aligned.m16n8k16.row.col.f32.bf16.bf16.f32 "
        "{%0,%1,%2,%3}, {%4,%5,%6,%7}, {%8,%9}, {%0,%1,%2,%3};"
        : "+f"(c[0]), "+f"(c[1]), "+f"(c[2]), "+f"(c[3])
        : "r"(a[0]), "r"(a[1]), "r"(a[2]), "r"(a[3]), "r"(b0), "r"(b1));
}
__device__ __forceinline__ void top2_merge(float& v1, int& x1, float& v2,
                                           float ov1, int ox1, float ov2) {
    float lo = fminf(v1, ov1);
    if (ov1 > v1)               { v1 = ov1; x1 = ox1; }
    else if (ov1 == v1 && ox1 < x1) x1 = ox1;
    v2 = fmaxf(v2, fmaxf(lo, ov2));
}

// ---------------------------------------------------------------------------
__device__ __forceinline__ float sext_fwd(const float* __restrict__ tg, int idx) {
    int m = idx / 3, c = idx - m * 3;
    int mm = (m >= Nn) ? (m - Nn) : m;
    return tg[mm * 3 + c];
}
__device__ __forceinline__ float sext_bwd(const float* __restrict__ tg, int idx) {
    int m = idx / 3, c = idx - m * 3;
    int mm = (m >= Nn) ? (m - Nn) : m;
    return tg[(Nn - 1 - mm) * 3 + c];
}

// ---------------------------------------------------------------------------
// pre: blocks 0..3 softmax; 4..131 p2 (warp/q); 132..163 v2 (warp/t); 164 labels+perm
__global__ void pre_kernel(const float* __restrict__ pred,
                           const float* __restrict__ vlog,
                           const float* __restrict__ tlog,
                           const float* __restrict__ clog,
                           const float* __restrict__ tgt,
                           const int* __restrict__ lab32,
                           const int* __restrict__ clo32)
{
    const int tid = threadIdx.x;
    const int bx  = blockIdx.x;
    if (bx < 4) {
        const int q = bx * 256 + tid;
        float x0 = tlog[q*4+0], x1 = tlog[q*4+1], x2 = tlog[q*4+2], x3 = tlog[q*4+3];
        float m  = fmaxf(fmaxf(x0, x1), fmaxf(x2, x3));
        float e0 = expf(x0-m), e1 = expf(x1-m), e2 = expf(x2-m), e3 = expf(x3-m);
        float s  = e0 + e1 + e2 + e3;
        g_cls[q*8+0] = logf(e0/s + 1e-6f);
        g_cls[q*8+1] = logf(e1/s + 1e-6f);
        g_cls[q*8+2] = logf(e2/s + 1e-6f);
        g_cls[q*8+3] = logf(e3/s + 1e-6f);
        float a0 = vlog[q*2+0], a1 = vlog[q*2+1];
        float ma = fmaxf(a0, a1);
        float f0 = expf(a0-ma), f1 = expf(a1-ma);
        g_cls[q*8+4] = logf(f0/(f0+f1) + 1e-6f);
        float b0 = clog[q*2+0], b1 = clog[q*2+1];
        float mb = fmaxf(b0, b1);
        float h0 = expf(b0-mb), h1 = expf(b1-mb);
        float hs = h0 + h1;
        g_cls[q*8+5] = logf(h0/hs + 1e-6f);
        g_cls[q*8+6] = logf(h1/hs + 1e-6f);
    } else if (bx < 132) {
        // p2: warp per q, lane-strided reduce over 300
        const int q    = (bx - 4) * 8 + (tid >> 5);
        const int lane = tid & 31;
        const float* p = pred + q * Kn;
        float s = 0.f;
        #pragma unroll
        for (int j = 0; j < 10; j++) {
            int k = lane + 32 * j;
            if (k < Kn) { float v = p[k]; s = fmaf(v, v, s); }
        }
        #pragma unroll
        for (int m = 16; m >= 1; m >>= 1) s += __shfl_xor_sync(0xffffffffu, s, m);
        if (lane == 0) g_cls[q*8+7] = s;
    } else if (bx < 164) {
        // v2: warp per t
        const int t    = (bx - 132) * 8 + (tid >> 5);
        const int lane = tid & 31;
        const float* p = tgt + t * Kn;
        float s = 0.f;
        #pragma unroll
        for (int j = 0; j < 10; j++) {
            int k = lane + 32 * j;
            if (k < Kn) { float v = p[k]; s = fmaf(v, v, s); }
        }
        #pragma unroll
        for (int m = 16; m >= 1; m >>= 1) s += __shfl_xor_sync(0xffffffffu, s, m);
        if (lane == 0) g_v2[t] = s;
    } else {
        if (tid == 0) g_fcnt = 0;   // reset rescue list each launch (graph replays)
        __shared__ int flag;
        if (tid == 0) flag = 0;
        __syncthreads();
        if (tid < 128) {
            if (lab32[2*tid+1] != 0 || clo32[2*tid+1] != 0) atomicOr(&flag, 1);
        }
        __syncthreads();
        const int t = tid;
        int lv, cv;
        if (flag) { lv = lab32[t]; cv = clo32[t]; }
        else {
            lv = (int)((const long long*)lab32)[t];
            cv = (int)((const long long*)clo32)[t];
        }
        g_lab[t] = lv;
        g_clo[t] = cv;
        __syncthreads();
        if (tid == 0) {
            int a = 0, b = 0;
            for (int i = 0; i < Tn; i++) if (g_clo[i]) g_tperm[a++] = i;
            for (int i = 0; i < Tn; i++) if (!g_clo[i]) g_tperm[a + (b++)] = i;
        }
    }
}

// bf16 hi/lo planes for preds and target pair tables
__global__ void pre2_kernel(const float* __restrict__ pred,
                            const float* __restrict__ tgt)
{
    int idx = blockIdx.x * 256 + threadIdx.x;
    if (blockIdx.x < 1280) {
        int q = idx / KP, k = idx - q * KP;
        float x = (k < Kn) ? pred[q * Kn + k] : 0.f;
        __nv_bfloat16 hi = __float2bfloat16(x);
        g_pb_hi[idx] = hi;
        g_pb_lo[idx] = __float2bfloat16(x - __bfloat162float(hi));
    } else {
        int i2 = idx - 1280 * 256;
        if (i2 >= 2 * Tn * 648) return;
        int dt = i2 / 648, j = i2 - dt * 648;
        int dir = dt >> 8, t = dt & 255;
        const float* tg = tgt + t * Kn;
        float x0 = 0.f, x1 = 0.f;
        if (j < 600)     x0 = dir ? sext_bwd(tg, j)     : sext_fwd(tg, j);
        if (j + 1 < 600) x1 = dir ? sext_bwd(tg, j + 1) : sext_fwd(tg, j + 1);
        __nv_bfloat16 h0 = __float2bfloat16(x0), h1 = __float2bfloat16(x1);
        __nv_bfloat16 l0 = __float2bfloat16(x0 - __bfloat162float(h0));
        __nv_bfloat16 l1 = __float2bfloat16(x1 - __bfloat162float(h1));
        g_sp_hi[i2] = (unsigned)__bfloat16_as_ushort(h0) | ((unsigned)__bfloat16_as_ushort(h1) << 16);
        g_sp_lo[i2] = (unsigned)__bfloat16_as_ushort(l0) | ((unsigned)__bfloat16_as_ushort(l1) << 16);
    }
}

// ---------------------------------------------------------------------------
__device__ __forceinline__ void epilogue_write(
    float best_ab, int ids, int t, int q, int clos,
    const float* __restrict__ clw, float* __restrict__ out, int write_ids)
{
    const float p2 = g_cls[q*8+7];
    float d2 = fmaxf(g_v2[t] + p2 - 2.0f * best_ab, 0.0f) / 100.0f;
    const int lab = g_lab[t];
    float cls = g_cls[q*8+lab] + g_cls[q*8+4] + g_cls[q*8+5+clos];
    float C = d2 * clw[t] - cls;
    out[q * Tn + t] = C;
    if (write_ids) out[Qn * Tn + q * Tn + t] = (float)ids;
}

// ---------------------------------------------------------------------------
// HMMA kernel: one CTA = (closed t, dir, 128-q tile). 8 warps = 4(M) x 2(N).
#define BPITCH 144
__global__ void __launch_bounds__(256, 2)
mma_kernel(int write_ids)
{
    __shared__ unsigned ssph[648], sspl[648];
    __shared__ char sB[2][128 * BPITCH];
    __shared__ float redv[4][128];
    __shared__ int   redi[4][128];
    __shared__ float redv2[4][128];

    const int tid  = threadIdx.x;
    const int wid  = tid >> 5, lane = tid & 31;
    const int wm   = wid & 3,  wn = wid >> 2;
    const int t    = g_tperm[blockIdx.x];
    if (!g_clo[t]) return;
    const int dir  = blockIdx.y >> 3;
    const int q0   = (blockIdx.y & 7) * 128;
    const int m0   = wm * 32;
    const int n0   = wn * 64;
    const int g    = lane >> 2;
    const int t2   = (lane & 3) * 2;

    {
        const unsigned* gh = g_sp_hi + (dir * Tn + t) * 648;
        const unsigned* gl = g_sp_lo + (dir * Tn + t) * 648;
        for (int j = tid; j < 648; j += 256) { ssph[j] = gh[j]; sspl[j] = gl[j]; }
    }

    float c[2][8][4];
    #pragma unroll
    for (int mt = 0; mt < 2; mt++)
        #pragma unroll
        for (int nt = 0; nt < 8; nt++)
            #pragma unroll
            for (int r = 0; r < 4; r++) c[mt][nt][r] = 0.f;

    int off0[2], off1[2];
    bool val0[2], val1[2];
    #pragma unroll
    for (int mt = 0; mt < 2; mt++) {
        int v0 = m0 + mt * 16 + g;
        val0[mt] = (v0 < 100);
        val1[mt] = (v0 + 8 < 100);
        off0[mt] = val0[mt] ? 3 * (100 - v0) : 0;
        off1[mt] = val1[mt] ? 3 * (100 - v0) - 24 : 0;
    }

    for (int kc = 0; kc < 5; kc++) {
        __syncthreads();
        #pragma unroll
        for (int plane = 0; plane < 2; plane++) {
            const __nv_bfloat16* src = (plane ? g_pb_lo : g_pb_hi);
            for (int i = tid; i < 128 * 16; i += 256) {
                int row = i >> 4, w = i & 15;
                u64 v = *(const u64*)(src + (u64)(q0 + row) * KP + kc * 64 + w * 4);
                *(u64*)(sB[plane] + row * BPITCH + w * 8) = v;
            }
        }
        __syncthreads();

        #pragma unroll
        for (int ks = 0; ks < 4; ks++) {
            const int kk = kc * 64 + ks * 16 + t2;
            unsigned ah[2][4], al[2][4];
            #pragma unroll
            for (int mt = 0; mt < 2; mt++) {
                ah[mt][0] = val0[mt] ? ssph[off0[mt] + kk]     : 0u;
                ah[mt][1] = val1[mt] ? ssph[off1[mt] + kk]     : 0u;
                ah[mt][2] = val0[mt] ? ssph[off0[mt] + kk + 8] : 0u;
                ah[mt][3] = val1[mt] ? ssph[off1[mt] + kk + 8] : 0u;
                al[mt][0] = val0[mt] ? sspl[off0[mt] + kk]     : 0u;
                al[mt][1] = val1[mt] ? sspl[off1[mt] + kk]     : 0u;
                al[mt][2] = val0[mt] ? sspl[off0[mt] + kk + 8] : 0u;
                al[mt][3] = val1[mt] ? sspl[off1[mt] + kk + 8] : 0u;
            }
            #pragma unroll
            for (int nt = 0; nt < 8; nt++) {
                const int brow = n0 + nt * 8 + g;
                const char* bh = sB[0] + brow * BPITCH + (ks * 16 + t2) * 2;
                const char* bl = sB[1] + brow * BPITCH + (ks * 16 + t2) * 2;
                unsigned bh0 = *(const unsigned*)bh;
                unsigned bh1 = *(const unsigned*)(bh + 16);
                unsigned bl0 = *(const unsigned*)bl;
                unsigned bl1 = *(const unsigned*)(bl + 16);
                #pragma unroll
                for (int mt = 0; mt < 2; mt++) {
                    mma16816(c[mt][nt], ah[mt], bh0, bh1);
                    mma16816(c[mt][nt], al[mt], bh0, bh1);
                    mma16816(c[mt][nt], ah[mt], bl0, bl1);
                }
            }
        }
    }

    // ---- epilogue: top-2 argmax over v per q column ----
    const float NINF = -__int_as_float(0x7f800000);
    #pragma unroll
    for (int nt = 0; nt < 8; nt++) {
        #pragma unroll
        for (int cp = 0; cp < 2; cp++) {
            float bv = NINF; int bx = 127; float bv2 = NINF;
            #pragma unroll
            for (int mt = 0; mt < 2; mt++) {
                #pragma unroll
                for (int rh = 0; rh < 2; rh++) {
                    int v = m0 + mt * 16 + rh * 8 + g;
                    float val = (v < 100) ? c[mt][nt][rh * 2 + cp] : NINF;
                    top2_merge(bv, bx, bv2, val, v, NINF);
                }
            }
            #pragma unroll
            for (int m = 4; m <= 16; m <<= 1) {
                float ov  = __shfl_xor_sync(0xffffffffu, bv, m);
                int   ox  = __shfl_xor_sync(0xffffffffu, bx, m);
                float ov2 = __shfl_xor_sync(0xffffffffu, bv2, m);
                top2_merge(bv, bx, bv2, ov, ox, ov2);
            }
            if (lane < 4) {
                int col = n0 + nt * 8 + t2 + cp;
                redv[wm][col]  = bv;
                redi[wm][col]  = bx;
                redv2[wm][col] = bv2;
            }
        }
    }
    __syncthreads();
    if (tid < 128) {
        int col = tid;
        float bv = redv[0][col]; int bx = redi[0][col]; float bv2 = redv2[0][col];
        #pragma unroll
        for (int w = 1; w < 4; w++)
            top2_merge(bv, bx, bv2, redv[w][col], redi[w][col], redv2[w][col]);
        int o = (dir * Tn + t) * Qn + q0 + col;
        g_pab[o] = bv; g_pix[o] = bx; g_pv2[o] = bv2;
    }
}

// ---------------------------------------------------------------------------
__global__ void combine_kernel(const float* __restrict__ clw,
                               float* __restrict__ out, int write_ids)
{
    int idx = blockIdx.x * 256 + threadIdx.x;
    int t = idx >> 10, q = idx & 1023;
    if (!g_clo[t]) return;
    float f1 = g_pab[t * Qn + q];        int xf = g_pix[t * Qn + q];
    float f2 = g_pv2[t * Qn + q];
    float w1 = g_pab[(Tn + t) * Qn + q]; int xb = g_pix[(Tn + t) * Qn + q];
    float w2 = g_pv2[(Tn + t) * Qn + q];
    float best, second; int ids;
    if (w1 > f1) { best = w1; ids = 99 - xb; second = fmaxf(f1, w2); }
    else         { best = f1; ids = xf;      second = fmaxf(w1, f2); }
    epilogue_write(best, ids, t, q, 1, clw, out, write_ids);
    if (best - second < EPSGAP) {
        int slot = atomicAdd(&g_fcnt, 1);
        g_flist[slot] = (t << 10) | q;
    }
}

// ---------------------------------------------------------------------------
// exact fp32 rescue: one warp per ambiguous (t,q), all 200 variants
__global__ void __launch_bounds__(256)
rescue_kernel(const float* __restrict__ pred, const float* __restrict__ tgt,
              const float* __restrict__ clw, float* __restrict__ out, int write_ids)
{
    const int lane = threadIdx.x & 31;
    const int gw   = (blockIdx.x * 256 + threadIdx.x) >> 5;
    const int nw   = gridDim.x * 8;
    const int n    = g_fcnt;
    const float NINF = -__int_as_float(0x7f800000);
    for (int i = gw; i < n; i += nw) {
        int code = g_flist[i];
        int t = code >> 10, q = code & 1023;
        const float* tg = tgt + t * Kn;
        const float* pq = pred + q * Kn;
        float bv = NINF; int bx = 255;
        for (int r = lane; r < 200; r += 32) {
            int  sh  = (r < 100) ? (100 - r) : (200 - r);
            bool rev = (r >= 100);
            float c0 = 0.f, c1 = 0.f, c2 = 0.f;
            for (int j = 0; j < 100; j++) {
                int jj = j + sh; if (jj >= 100) jj -= 100;
                int row = rev ? (99 - jj) : jj;
                c0 = fmaf(pq[j*3+0], tg[row*3+0], c0);
                c1 = fmaf(pq[j*3+1], tg[row*3+1], c1);
                c2 = fmaf(pq[j*3+2], tg[row*3+2], c2);
            }
            float ab = c0 + c1 + c2;
            if (ab > bv) { bv = ab; bx = r; }
        }
        #pragma unroll
        for (int m = 16; m >= 1; m >>= 1) {
            float ov = __shfl_xor_sync(0xffffffffu, bv, m);
            int   ox = __shfl_xor_sync(0xffffffffu, bx, m);
            if (ov > bv || (ov == bv && ox < bx)) { bv = ov; bx = ox; }
        }
        if (lane == 0) {
            int ids = (bx < 100) ? bx : 199 - bx;
            epilogue_write(bv, ids, t, q, 1, clw, out, write_ids);
        }
    }
}

// ---------------------------------------------------------------------------
// open curves: variants v=0 (fwd) and v=n (bwd), fp32, high-MLP
__global__ void __launch_bounds__(256)
light_kernel(const float* __restrict__ pred, const float* __restrict__ tgt,
             const float* __restrict__ clw, float* __restrict__ out, int write_ids)
{
    __shared__ float2 pf[152], pb2[152];
    const int t = blockIdx.x;
    if (g_clo[t]) return;
    const int q = blockIdx.y * 256 + threadIdx.x;
    const float* tg = tgt + t * Kn;
    for (int i = threadIdx.x; i < 150; i += 256) {
        int j = 300 + 2 * i;
        pf[i]  = make_float2(sext_fwd(tg, j), sext_fwd(tg, j + 1));
        pb2[i] = make_float2(sext_bwd(tg, j), sext_bwd(tg, j + 1));
    }
    __syncthreads();
    const float4* p4  = (const float4*)(pred + q * Kn);   // 1200B row: 16B aligned
    const u64*    suf = (const u64*)pf;
    const u64*    sub = (const u64*)pb2;
    u64 af0 = 0ull, af1 = 0ull, ab0 = 0ull, ab1 = 0ull;
    #pragma unroll 5
    for (int i = 0; i < 75; i++) {
        float4 p = p4[i];
        u64 plo, phi;
        asm("mov.b64 %0, {%2, %3}; mov.b64 %1, {%4, %5};"
            : "=l"(plo), "=l"(phi) : "f"(p.x), "f"(p.y), "f"(p.z), "f"(p.w));
        ffma2(af0, plo, suf[2*i]);
        ffma2(af1, phi, suf[2*i+1]);
        ffma2(ab0, plo, sub[2*i]);
        ffma2(ab1, phi, sub[2*i+1]);
    }
    float af = pairsum(af0) + pairsum(af1);
    float ab = pairsum(ab0) + pairsum(ab1);
    epilogue_write(fmaxf(af, ab), 0, t, q, 0, clw, out, write_ids);
}

// ---------------------------------------------------------------------------
extern "C" void kernel_launch(void* const* d_in, const int* in_sizes, int n_in,
                              void* d_out, int out_size)
{
    const float* pred = (const float*)d_in[0];
    const float* vlog = (const float*)d_in[1];
    const float* tlog = (const float*)d_in[2];
    const float* clog = (const float*)d_in[3];
    const float* tgt  = (const float*)d_in[4];
    const int*   lab  = (const int*)d_in[5];
    const int*   clo  = (const int*)d_in[6];
    const float* clw  = (const float*)d_in[7];
    float* out = (float*)d_out;

    const int write_ids = (out_size >= 2 * Qn * Tn) ? 1 : 0;

    pre_kernel<<<165, 256>>>(pred, vlog, tlog, clog, tgt, lab, clo);
    pre2_kernel<<<1280 + 1296, 256>>>(pred, tgt);
    mma_kernel<<<dim3(Tn, 16), 256>>>(write_ids);
    light_kernel<<<dim3(Tn, 4), 256>>>(pred, tgt, clw, out, write_ids);
    combine_kernel<<<1024, 256>>>(clw, out, write_ids);
    rescue_kernel<<<512, 256>>>(pred, tgt, clw, out, write_ids);
}

// round 11
// speedup vs baseline: 1.8614x; 1.0528x over previous
#include <cuda_runtime.h>
#include <cuda_bf16.h>
#include <math.h>

#define Qn 1024
#define Tn 256
#define Nn 100
#define Kn 300
#define KP 320          // padded K (5 chunks of 64)
#define EPSGAP 0.02f    // bf16-path ambiguity threshold for exact rescue

typedef unsigned long long u64;

__device__ float g_cls[Qn * 8];
__device__ float g_v2[Tn];
__device__ int   g_lab[Tn];
__device__ int   g_clo[Tn];
__device__ int   g_tperm[Tn];
__device__ __nv_bfloat16 g_pb_hi[Qn * KP];   // pred bf16 hi plane, [q][KP]
__device__ __nv_bfloat16 g_pb_lo[Qn * KP];   // residual plane
__device__ unsigned g_sp_hi[2 * Tn * 648];   // extended-target pair table (bf16x2), hi
__device__ unsigned g_sp_lo[2 * Tn * 648];   // lo
__device__ float g_predT[Kn * Qn];           // transposed pred [k][q] for coalesced light path
__device__ float g_pab[2 * Tn * Qn];         // per-(dir,t,q) best ab
__device__ int   g_pix[2 * Tn * Qn];         // its v index
__device__ float g_pv2[2 * Tn * Qn];         // runner-up ab
__device__ int   g_flist[Tn * Qn];           // flagged (t<<10|q)
__device__ int   g_fcnt;

__device__ __forceinline__ void mma16816(float* c, const unsigned* a, unsigned b0, unsigned b1) {
    asm volatile(
        "mma.sync.aligned.m16n8k16.row.col.f32.bf16.bf16.f32 "
        "{%0,%1,%2,%3}, {%4,%5,%6,%7}, {%8,%9}, {%0,%1,%2,%3};"
        : "+f"(c[0]), "+f"(c[1]), "+f"(c[2]), "+f"(c[3])
        : "r"(a[0]), "r"(a[1]), "r"(a[2]), "r"(a[3]), "r"(b0), "r"(b1));
}
__device__ __forceinline__ void top2_merge(float& v1, int& x1, float& v2,
                                           float ov1, int ox1, float ov2) {
    float lo = fminf(v1, ov1);
    if (ov1 > v1)               { v1 = ov1; x1 = ox1; }
    else if (ov1 == v1 && ox1 < x1) x1 = ox1;
    v2 = fmaxf(v2, fmaxf(lo, ov2));
}

// ---------------------------------------------------------------------------
__device__ __forceinline__ float sext_fwd(const float* __restrict__ tg, int idx) {
    int m = idx / 3, c = idx - m * 3;
    int mm = (m >= Nn) ? (m - Nn) : m;
    return tg[mm * 3 + c];
}
__device__ __forceinline__ float sext_bwd(const float* __restrict__ tg, int idx) {
    int m = idx / 3, c = idx - m * 3;
    int mm = (m >= Nn) ? (m - Nn) : m;
    return tg[(Nn - 1 - mm) * 3 + c];
}

// ---------------------------------------------------------------------------
// pre: blocks 0..3 softmax; 4..131 p2 (warp/q); 132..163 v2 (warp/t); 164 labels+perm
__global__ void pre_kernel(const float* __restrict__ pred,
                           const float* __restrict__ vlog,
                           const float* __restrict__ tlog,
                           const float* __restrict__ clog,
                           const float* __restrict__ tgt,
                           const int* __restrict__ lab32,
                           const int* __restrict__ clo32)
{
    const int tid = threadIdx.x;
    const int bx  = blockIdx.x;
    if (bx < 4) {
        const int q = bx * 256 + tid;
        float x0 = tlog[q*4+0], x1 = tlog[q*4+1], x2 = tlog[q*4+2], x3 = tlog[q*4+3];
        float m  = fmaxf(fmaxf(x0, x1), fmaxf(x2, x3));
        float e0 = expf(x0-m), e1 = expf(x1-m), e2 = expf(x2-m), e3 = expf(x3-m);
        float s  = e0 + e1 + e2 + e3;
        g_cls[q*8+0] = logf(e0/s + 1e-6f);
        g_cls[q*8+1] = logf(e1/s + 1e-6f);
        g_cls[q*8+2] = logf(e2/s + 1e-6f);
        g_cls[q*8+3] = logf(e3/s + 1e-6f);
        float a0 = vlog[q*2+0], a1 = vlog[q*2+1];
        float ma = fmaxf(a0, a1);
        float f0 = expf(a0-ma), f1 = expf(a1-ma);
        g_cls[q*8+4] = logf(f0/(f0+f1) + 1e-6f);
        float b0 = clog[q*2+0], b1 = clog[q*2+1];
        float mb = fmaxf(b0, b1);
        float h0 = expf(b0-mb), h1 = expf(b1-mb);
        float hs = h0 + h1;
        g_cls[q*8+5] = logf(h0/hs + 1e-6f);
        g_cls[q*8+6] = logf(h1/hs + 1e-6f);
    } else if (bx < 132) {
        const int q    = (bx - 4) * 8 + (tid >> 5);
        const int lane = tid & 31;
        const float* p = pred + q * Kn;
        float s = 0.f;
        #pragma unroll
        for (int j = 0; j < 10; j++) {
            int k = lane + 32 * j;
            if (k < Kn) { float v = p[k]; s = fmaf(v, v, s); }
        }
        #pragma unroll
        for (int m = 16; m >= 1; m >>= 1) s += __shfl_xor_sync(0xffffffffu, s, m);
        if (lane == 0) g_cls[q*8+7] = s;
    } else if (bx < 164) {
        const int t    = (bx - 132) * 8 + (tid >> 5);
        const int lane = tid & 31;
        const float* p = tgt + t * Kn;
        float s = 0.f;
        #pragma unroll
        for (int j = 0; j < 10; j++) {
            int k = lane + 32 * j;
            if (k < Kn) { float v = p[k]; s = fmaf(v, v, s); }
        }
        #pragma unroll
        for (int m = 16; m >= 1; m >>= 1) s += __shfl_xor_sync(0xffffffffu, s, m);
        if (lane == 0) g_v2[t] = s;
    } else {
        if (tid == 0) g_fcnt = 0;   // reset rescue list each launch (graph replays)
        __shared__ int flag;
        if (tid == 0) flag = 0;
        __syncthreads();
        if (tid < 128) {
            if (lab32[2*tid+1] != 0 || clo32[2*tid+1] != 0) atomicOr(&flag, 1);
        }
        __syncthreads();
        const int t = tid;
        int lv, cv;
        if (flag) { lv = lab32[t]; cv = clo32[t]; }
        else {
            lv = (int)((const long long*)lab32)[t];
            cv = (int)((const long long*)clo32)[t];
        }
        g_lab[t] = lv;
        g_clo[t] = cv;
        __syncthreads();
        if (tid == 0) {
            int a = 0, b = 0;
            for (int i = 0; i < Tn; i++) if (g_clo[i]) g_tperm[a++] = i;
            for (int i = 0; i < Tn; i++) if (!g_clo[i]) g_tperm[a + (b++)] = i;
        }
    }
}

// bf16 hi/lo planes, target pair tables, and pred transpose
__global__ void pre2_kernel(const float* __restrict__ pred,
                            const float* __restrict__ tgt)
{
    int idx = blockIdx.x * 256 + threadIdx.x;
    if (blockIdx.x < 1280) {
        int q = idx / KP, k = idx - q * KP;
        float x = (k < Kn) ? pred[q * Kn + k] : 0.f;
        __nv_bfloat16 hi = __float2bfloat16(x);
        g_pb_hi[idx] = hi;
        g_pb_lo[idx] = __float2bfloat16(x - __bfloat162float(hi));
    } else if (blockIdx.x < 2576) {
        int i2 = idx - 1280 * 256;
        if (i2 >= 2 * Tn * 648) return;
        int dt = i2 / 648, j = i2 - dt * 648;
        int dir = dt >> 8, t = dt & 255;
        const float* tg = tgt + t * Kn;
        float x0 = 0.f, x1 = 0.f;
        if (j < 600)     x0 = dir ? sext_bwd(tg, j)     : sext_fwd(tg, j);
        if (j + 1 < 600) x1 = dir ? sext_bwd(tg, j + 1) : sext_fwd(tg, j + 1);
        __nv_bfloat16 h0 = __float2bfloat16(x0), h1 = __float2bfloat16(x1);
        __nv_bfloat16 l0 = __float2bfloat16(x0 - __bfloat162float(h0));
        __nv_bfloat16 l1 = __float2bfloat16(x1 - __bfloat162float(h1));
        g_sp_hi[i2] = (unsigned)__bfloat16_as_ushort(h0) | ((unsigned)__bfloat16_as_ushort(h1) << 16);
        g_sp_lo[i2] = (unsigned)__bfloat16_as_ushort(l0) | ((unsigned)__bfloat16_as_ushort(l1) << 16);
    } else {
        // transpose: g_predT[k*Qn + q] = pred[q*Kn + k]; coalesced writes
        int i3 = idx - 2576 * 256;           // 0 .. 307199
        int k = i3 >> 10, q = i3 & 1023;
        g_predT[i3] = pred[q * Kn + k];
    }
}

// ---------------------------------------------------------------------------
__device__ __forceinline__ void epilogue_write(
    float best_ab, int ids, int t, int q, int clos,
    const float* __restrict__ clw, float* __restrict__ out, int write_ids)
{
    const float p2 = g_cls[q*8+7];
    float d2 = fmaxf(g_v2[t] + p2 - 2.0f * best_ab, 0.0f) / 100.0f;
    const int lab = g_lab[t];
    float cls = g_cls[q*8+lab] + g_cls[q*8+4] + g_cls[q*8+5+clos];
    float C = d2 * clw[t] - cls;
    out[q * Tn + t] = C;
    if (write_ids) out[Qn * Tn + q * Tn + t] = (float)ids;
}

// ---------------------------------------------------------------------------
// HMMA kernel: one CTA = (closed t, dir, 128-q tile). 8 warps = 4(M) x 2(N).
#define BPITCH 144
__global__ void __launch_bounds__(256, 2)
mma_kernel(int write_ids)
{
    __shared__ unsigned ssph[648], sspl[648];
    __shared__ char sB[2][128 * BPITCH];
    __shared__ float redv[4][128];
    __shared__ int   redi[4][128];
    __shared__ float redv2[4][128];

    const int tid  = threadIdx.x;
    const int wid  = tid >> 5, lane = tid & 31;
    const int wm   = wid & 3,  wn = wid >> 2;
    const int t    = g_tperm[blockIdx.x];
    if (!g_clo[t]) return;
    const int dir  = blockIdx.y >> 3;
    const int q0   = (blockIdx.y & 7) * 128;
    const int m0   = wm * 32;
    const int n0   = wn * 64;
    const int g    = lane >> 2;
    const int t2   = (lane & 3) * 2;

    {
        const unsigned* gh = g_sp_hi + (dir * Tn + t) * 648;
        const unsigned* gl = g_sp_lo + (dir * Tn + t) * 648;
        for (int j = tid; j < 648; j += 256) { ssph[j] = gh[j]; sspl[j] = gl[j]; }
    }

    float c[2][8][4];
    #pragma unroll
    for (int mt = 0; mt < 2; mt++)
        #pragma unroll
        for (int nt = 0; nt < 8; nt++)
            #pragma unroll
            for (int r = 0; r < 4; r++) c[mt][nt][r] = 0.f;

    int off0[2], off1[2];
    bool val0[2], val1[2];
    #pragma unroll
    for (int mt = 0; mt < 2; mt++) {
        int v0 = m0 + mt * 16 + g;
        val0[mt] = (v0 < 100);
        val1[mt] = (v0 + 8 < 100);
        off0[mt] = val0[mt] ? 3 * (100 - v0) : 0;
        off1[mt] = val1[mt] ? 3 * (100 - v0) - 24 : 0;
    }

    for (int kc = 0; kc < 5; kc++) {
        __syncthreads();
        #pragma unroll
        for (int plane = 0; plane < 2; plane++) {
            const __nv_bfloat16* src = (plane ? g_pb_lo : g_pb_hi);
            for (int i = tid; i < 128 * 16; i += 256) {
                int row = i >> 4, w = i & 15;
                u64 v = *(const u64*)(src + (u64)(q0 + row) * KP + kc * 64 + w * 4);
                *(u64*)(sB[plane] + row * BPITCH + w * 8) = v;
            }
        }
        __syncthreads();

        #pragma unroll
        for (int ks = 0; ks < 4; ks++) {
            const int kk = kc * 64 + ks * 16 + t2;
            unsigned ah[2][4], al[2][4];
            #pragma unroll
            for (int mt = 0; mt < 2; mt++) {
                ah[mt][0] = val0[mt] ? ssph[off0[mt] + kk]     : 0u;
                ah[mt][1] = val1[mt] ? ssph[off1[mt] + kk]     : 0u;
                ah[mt][2] = val0[mt] ? ssph[off0[mt] + kk + 8] : 0u;
                ah[mt][3] = val1[mt] ? ssph[off1[mt] + kk + 8] : 0u;
                al[mt][0] = val0[mt] ? sspl[off0[mt] + kk]     : 0u;
                al[mt][1] = val1[mt] ? sspl[off1[mt] + kk]     : 0u;
                al[mt][2] = val0[mt] ? sspl[off0[mt] + kk + 8] : 0u;
                al[mt][3] = val1[mt] ? sspl[off1[mt] + kk + 8] : 0u;
            }
            #pragma unroll
            for (int nt = 0; nt < 8; nt++) {
                const int brow = n0 + nt * 8 + g;
                const char* bh = sB[0] + brow * BPITCH + (ks * 16 + t2) * 2;
                const char* bl = sB[1] + brow * BPITCH + (ks * 16 + t2) * 2;
                unsigned bh0 = *(const unsigned*)bh;
                unsigned bh1 = *(const unsigned*)(bh + 16);
                unsigned bl0 = *(const unsigned*)bl;
                unsigned bl1 = *(const unsigned*)(bl + 16);
                #pragma unroll
                for (int mt = 0; mt < 2; mt++) {
                    mma16816(c[mt][nt], ah[mt], bh0, bh1);
                    mma16816(c[mt][nt], al[mt], bh0, bh1);
                    mma16816(c[mt][nt], ah[mt], bl0, bl1);
                }
            }
        }
    }

    // ---- epilogue: top-2 argmax over v per q column ----
    const float NINF = -__int_as_float(0x7f800000);
    #pragma unroll
    for (int nt = 0; nt < 8; nt++) {
        #pragma unroll
        for (int cp = 0; cp < 2; cp++) {
            float bv = NINF; int bx = 127; float bv2 = NINF;
            #pragma unroll
            for (int mt = 0; mt < 2; mt++) {
                #pragma unroll
                for (int rh = 0; rh < 2; rh++) {
                    int v = m0 + mt * 16 + rh * 8 + g;
                    float val = (v < 100) ? c[mt][nt][rh * 2 + cp] : NINF;
                    top2_merge(bv, bx, bv2, val, v, NINF);
                }
            }
            #pragma unroll
            for (int m = 4; m <= 16; m <<= 1) {
                float ov  = __shfl_xor_sync(0xffffffffu, bv, m);
                int   ox  = __shfl_xor_sync(0xffffffffu, bx, m);
                float ov2 = __shfl_xor_sync(0xffffffffu, bv2, m);
                top2_merge(bv, bx, bv2, ov, ox, ov2);
            }
            if (lane < 4) {
                int col = n0 + nt * 8 + t2 + cp;
                redv[wm][col]  = bv;
                redi[wm][col]  = bx;
                redv2[wm][col] = bv2;
            }
        }
    }
    __syncthreads();
    if (tid < 128) {
        int col = tid;
        float bv = redv[0][col]; int bx = redi[0][col]; float bv2 = redv2[0][col];
        #pragma unroll
        for (int w = 1; w < 4; w++)
            top2_merge(bv, bx, bv2, redv[w][col], redi[w][col], redv2[w][col]);
        int o = (dir * Tn + t) * Qn + q0 + col;
        g_pab[o] = bv; g_pix[o] = bx; g_pv2[o] = bv2;
    }
}

// ---------------------------------------------------------------------------
__global__ void combine_kernel(const float* __restrict__ clw,
                               float* __restrict__ out, int write_ids)
{
    int idx = blockIdx.x * 256 + threadIdx.x;
    int t = idx >> 10, q = idx & 1023;
    if (!g_clo[t]) return;
    float f1 = g_pab[t * Qn + q];        int xf = g_pix[t * Qn + q];
    float f2 = g_pv2[t * Qn + q];
    float w1 = g_pab[(Tn + t) * Qn + q]; int xb = g_pix[(Tn + t) * Qn + q];
    float w2 = g_pv2[(Tn + t) * Qn + q];
    float best, second; int ids;
    if (w1 > f1) { best = w1; ids = 99 - xb; second = fmaxf(f1, w2); }
    else         { best = f1; ids = xf;      second = fmaxf(w1, f2); }
    epilogue_write(best, ids, t, q, 1, clw, out, write_ids);
    if (best - second < EPSGAP) {
        int slot = atomicAdd(&g_fcnt, 1);
        g_flist[slot] = (t << 10) | q;
    }
}

// ---------------------------------------------------------------------------
// exact fp32 rescue: one warp per ambiguous (t,q), all 200 variants
__global__ void __launch_bounds__(256)
rescue_kernel(const float* __restrict__ pred, const float* __restrict__ tgt,
              const float* __restrict__ clw, float* __restrict__ out, int write_ids)
{
    const int lane = threadIdx.x & 31;
    const int gw   = (blockIdx.x * 256 + threadIdx.x) >> 5;
    const int nw   = gridDim.x * 8;
    const int n    = g_fcnt;
    const float NINF = -__int_as_float(0x7f800000);
    for (int i = gw; i < n; i += nw) {
        int code = g_flist[i];
        int t = code >> 10, q = code & 1023;
        const float* tg = tgt + t * Kn;
        const float* pq = pred + q * Kn;
        float bv = NINF; int bx = 255;
        for (int r = lane; r < 200; r += 32) {
            int  sh  = (r < 100) ? (100 - r) : (200 - r);
            bool rev = (r >= 100);
            float c0 = 0.f, c1 = 0.f, c2 = 0.f;
            for (int j = 0; j < 100; j++) {
                int jj = j + sh; if (jj >= 100) jj -= 100;
                int row = rev ? (99 - jj) : jj;
                c0 = fmaf(pq[j*3+0], tg[row*3+0], c0);
                c1 = fmaf(pq[j*3+1], tg[row*3+1], c1);
                c2 = fmaf(pq[j*3+2], tg[row*3+2], c2);
            }
            float ab = c0 + c1 + c2;
            if (ab > bv) { bv = ab; bx = r; }
        }
        #pragma unroll
        for (int m = 16; m >= 1; m >>= 1) {
            float ov = __shfl_xor_sync(0xffffffffu, bv, m);
            int   ox = __shfl_xor_sync(0xffffffffu, bx, m);
            if (ov > bv || (ov == bv && ox < bx)) { bv = ov; bx = ox; }
        }
        if (lane == 0) {
            int ids = (bx < 100) ? bx : 199 - bx;
            epilogue_write(bv, ids, t, q, 1, clw, out, write_ids);
        }
    }
}

// ---------------------------------------------------------------------------
// open curves: transposed coalesced loads, smem broadcast targets
__global__ void __launch_bounds__(256)
light_kernel(const float* __restrict__ tgt,
             const float* __restrict__ clw, float* __restrict__ out, int write_ids)
{
    __shared__ float sf[304], sb[304];
    const int t = blockIdx.x;
    if (g_clo[t]) return;
    const int q = blockIdx.y * 256 + threadIdx.x;
    const float* tg = tgt + t * Kn;
    for (int j = threadIdx.x; j < 300; j += 256) {
        sf[j] = sext_fwd(tg, j + 300);
        sb[j] = sext_bwd(tg, j + 300);
    }
    __syncthreads();
    float af0 = 0.f, af1 = 0.f, ab0 = 0.f, ab1 = 0.f;
    #pragma unroll 6
    for (int k = 0; k < Kn; k += 2) {
        float p0 = g_predT[k * Qn + q];
        float p1 = g_predT[(k + 1) * Qn + q];
        af0 = fmaf(p0, sf[k],     af0);
        af1 = fmaf(p1, sf[k + 1], af1);
        ab0 = fmaf(p0, sb[k],     ab0);
        ab1 = fmaf(p1, sb[k + 1], ab1);
    }
    epilogue_write(fmaxf(af0 + af1, ab0 + ab1), 0, t, q, 0, clw, out, write_ids);
}

// ---------------------------------------------------------------------------
extern "C" void kernel_launch(void* const* d_in, const int* in_sizes, int n_in,
                              void* d_out, int out_size)
{
    const float* pred = (const float*)d_in[0];
    const float* vlog = (const float*)d_in[1];
    const float* tlog = (const float*)d_in[2];
    const float* clog = (const float*)d_in[3];
    const float* tgt  = (const float*)d_in[4];
    const int*   lab  = (const int*)d_in[5];
    const int*   clo  = (const int*)d_in[6];
    const float* clw  = (const float*)d_in[7];
    float* out = (float*)d_out;

    const int write_ids = (out_size >= 2 * Qn * Tn) ? 1 : 0;

    pre_kernel<<<165, 256>>>(pred, vlog, tlog, clog, tgt, lab, clo);
    pre2_kernel<<<2576 + 1200, 256>>>(pred, tgt);
    mma_kernel<<<dim3(Tn, 16), 256>>>(write_ids);
    light_kernel<<<dim3(Tn, 4), 256>>>(tgt, clw, out, write_ids);
    combine_kernel<<<1024, 256>>>(clw, out, write_ids);
    rescue_kernel<<<512, 256>>>(pred, tgt, clw, out, write_ids);
}

// round 12
// speedup vs baseline: 1.9701x; 1.0584x over previous
#include <cuda_runtime.h>
#include <cuda_bf16.h>
#include <math.h>

#define Qn 1024
#define Tn 256
#define Nn 100
#define Kn 300
#define KP 320          // padded K (5 chunks of 64)
#define EPSGAP 0.02f    // bf16-path ambiguity threshold for exact rescue

typedef unsigned long long u64;

__device__ float g_cls[Qn * 8];
__device__ float g_v2[Tn];
__device__ int   g_lab[Tn];
__device__ int   g_clo[Tn];
__device__ int   g_tperm[Tn];
__device__ __nv_bfloat16 g_pb_hi[Qn * KP];   // pred bf16 hi plane, [q][KP]
__device__ __nv_bfloat16 g_pb_lo[Qn * KP];   // residual plane
__device__ unsigned g_sp_hi[2 * Tn * 648];   // extended-target pair table (bf16x2), hi
__device__ unsigned g_sp_lo[2 * Tn * 648];   // lo
__device__ float2 g_predT2[150 * Qn];        // transposed pred k-pairs [kp][q]
__device__ float g_pab[2 * Tn * Qn];         // per-(dir,t,q) best ab
__device__ int   g_pix[2 * Tn * Qn];         // its v index
__device__ float g_pv2[2 * Tn * Qn];         // runner-up ab
__device__ int   g_flist[Tn * Qn];           // flagged (t<<10|q)
__device__ int   g_fcnt;

__device__ __forceinline__ void ffma2(u64& c, u64 a, u64 b) {
    asm("fma.rn.f32x2 %0, %1, %2, %3;" : "=l"(c) : "l"(a), "l"(b), "l"(c));
}
__device__ __forceinline__ float pairsum(u64 v) {
    return __uint_as_float((unsigned)v) + __uint_as_float((unsigned)(v >> 32));
}
__device__ __forceinline__ void mma16816(float* c, const unsigned* a, unsigned b0, unsigned b1) {
    asm volatile(
        "mma.sync.aligned.m16n8k16.row.col.f32.bf16.bf16.f32 "
        "{%0,%1,%2,%3}, {%4,%5,%6,%7}, {%8,%9}, {%0,%1,%2,%3};"
        : "+f"(c[0]), "+f"(c[1]), "+f"(c[2]), "+f"(c[3])
        : "r"(a[0]), "r"(a[1]), "r"(a[2]), "r"(a[3]), "r"(b0), "r"(b1));
}
__device__ __forceinline__ void top2_merge(float& v1, int& x1, float& v2,
                                           float ov1, int ox1, float ov2) {
    float lo = fminf(v1, ov1);
    if (ov1 > v1)               { v1 = ov1; x1 = ox1; }
    else if (ov1 == v1 && ox1 < x1) x1 = ox1;
    v2 = fmaxf(v2, fmaxf(lo, ov2));
}

// ---------------------------------------------------------------------------
__device__ __forceinline__ float sext_fwd(const float* __restrict__ tg, int idx) {
    int m = idx / 3, c = idx - m * 3;
    int mm = (m >= Nn) ? (m - Nn) : m;
    return tg[mm * 3 + c];
}
__device__ __forceinline__ float sext_bwd(const float* __restrict__ tg, int idx) {
    int m = idx / 3, c = idx - m * 3;
    int mm = (m >= Nn) ? (m - Nn) : m;
    return tg[(Nn - 1 - mm) * 3 + c];
}

// ---------------------------------------------------------------------------
// pre: blocks 0..3 softmax; 4..131 p2 (warp/q); 132..163 v2 (warp/t); 164 labels+perm
__global__ void pre_kernel(const float* __restrict__ pred,
                           const float* __restrict__ vlog,
                           const float* __restrict__ tlog,
                           const float* __restrict__ clog,
                           const float* __restrict__ tgt,
                           const int* __restrict__ lab32,
                           const int* __restrict__ clo32)
{
    const int tid = threadIdx.x;
    const int bx  = blockIdx.x;
    if (bx < 4) {
        const int q = bx * 256 + tid;
        float x0 = tlog[q*4+0], x1 = tlog[q*4+1], x2 = tlog[q*4+2], x3 = tlog[q*4+3];
        float m  = fmaxf(fmaxf(x0, x1), fmaxf(x2, x3));
        float e0 = expf(x0-m), e1 = expf(x1-m), e2 = expf(x2-m), e3 = expf(x3-m);
        float s  = e0 + e1 + e2 + e3;
        g_cls[q*8+0] = logf(e0/s + 1e-6f);
        g_cls[q*8+1] = logf(e1/s + 1e-6f);
        g_cls[q*8+2] = logf(e2/s + 1e-6f);
        g_cls[q*8+3] = logf(e3/s + 1e-6f);
        float a0 = vlog[q*2+0], a1 = vlog[q*2+1];
        float ma = fmaxf(a0, a1);
        float f0 = expf(a0-ma), f1 = expf(a1-ma);
        g_cls[q*8+4] = logf(f0/(f0+f1) + 1e-6f);
        float b0 = clog[q*2+0], b1 = clog[q*2+1];
        float mb = fmaxf(b0, b1);
        float h0 = expf(b0-mb), h1 = expf(b1-mb);
        float hs = h0 + h1;
        g_cls[q*8+5] = logf(h0/hs + 1e-6f);
        g_cls[q*8+6] = logf(h1/hs + 1e-6f);
    } else if (bx < 132) {
        const int q    = (bx - 4) * 8 + (tid >> 5);
        const int lane = tid & 31;
        const float* p = pred + q * Kn;
        float s = 0.f;
        #pragma unroll
        for (int j = 0; j < 10; j++) {
            int k = lane + 32 * j;
            if (k < Kn) { float v = p[k]; s = fmaf(v, v, s); }
        }
        #pragma unroll
        for (int m = 16; m >= 1; m >>= 1) s += __shfl_xor_sync(0xffffffffu, s, m);
        if (lane == 0) g_cls[q*8+7] = s;
    } else if (bx < 164) {
        const int t    = (bx - 132) * 8 + (tid >> 5);
        const int lane = tid & 31;
        const float* p = tgt + t * Kn;
        float s = 0.f;
        #pragma unroll
        for (int j = 0; j < 10; j++) {
            int k = lane + 32 * j;
            if (k < Kn) { float v = p[k]; s = fmaf(v, v, s); }
        }
        #pragma unroll
        for (int m = 16; m >= 1; m >>= 1) s += __shfl_xor_sync(0xffffffffu, s, m);
        if (lane == 0) g_v2[t] = s;
    } else {
        if (tid == 0) g_fcnt = 0;   // reset rescue list each launch (graph replays)
        __shared__ int flag;
        if (tid == 0) flag = 0;
        __syncthreads();
        if (tid < 128) {
            if (lab32[2*tid+1] != 0 || clo32[2*tid+1] != 0) atomicOr(&flag, 1);
        }
        __syncthreads();
        const int t = tid;
        int lv, cv;
        if (flag) { lv = lab32[t]; cv = clo32[t]; }
        else {
            lv = (int)((const long long*)lab32)[t];
            cv = (int)((const long long*)clo32)[t];
        }
        g_lab[t] = lv;
        g_clo[t] = cv;
        __syncthreads();
        if (tid == 0) {
            int a = 0, b = 0;
            for (int i = 0; i < Tn; i++) if (g_clo[i]) g_tperm[a++] = i;
            for (int i = 0; i < Tn; i++) if (!g_clo[i]) g_tperm[a + (b++)] = i;
        }
    }
}

// bf16 hi/lo planes, target pair tables, and pred k-pair transpose
__global__ void pre2_kernel(const float* __restrict__ pred,
                            const float* __restrict__ tgt)
{
    int idx = blockIdx.x * 256 + threadIdx.x;
    if (blockIdx.x < 1280) {
        int q = idx / KP, k = idx - q * KP;
        float x = (k < Kn) ? pred[q * Kn + k] : 0.f;
        __nv_bfloat16 hi = __float2bfloat16(x);
        g_pb_hi[idx] = hi;
        g_pb_lo[idx] = __float2bfloat16(x - __bfloat162float(hi));
    } else if (blockIdx.x < 2576) {
        int i2 = idx - 1280 * 256;
        if (i2 >= 2 * Tn * 648) return;
        int dt = i2 / 648, j = i2 - dt * 648;
        int dir = dt >> 8, t = dt & 255;
        const float* tg = tgt + t * Kn;
        float x0 = 0.f, x1 = 0.f;
        if (j < 600)     x0 = dir ? sext_bwd(tg, j)     : sext_fwd(tg, j);
        if (j + 1 < 600) x1 = dir ? sext_bwd(tg, j + 1) : sext_fwd(tg, j + 1);
        __nv_bfloat16 h0 = __float2bfloat16(x0), h1 = __float2bfloat16(x1);
        __nv_bfloat16 l0 = __float2bfloat16(x0 - __bfloat162float(h0));
        __nv_bfloat16 l1 = __float2bfloat16(x1 - __bfloat162float(h1));
        g_sp_hi[i2] = (unsigned)__bfloat16_as_ushort(h0) | ((unsigned)__bfloat16_as_ushort(h1) << 16);
        g_sp_lo[i2] = (unsigned)__bfloat16_as_ushort(l0) | ((unsigned)__bfloat16_as_ushort(l1) << 16);
    } else {
        // k-pair transpose, q-major indexing: coalesced float2 reads, scattered stores
        int i3 = idx - 2576 * 256;           // 0 .. 153599
        if (i3 >= 150 * Qn) return;
        int q = i3 / 150, kp = i3 - q * 150;
        const float2 v = *(const float2*)(pred + q * Kn + 2 * kp);
        g_predT2[kp * Qn + q] = v;
    }
}

// ---------------------------------------------------------------------------
__device__ __forceinline__ void epilogue_write(
    float best_ab, int ids, int t, int q, int clos,
    const float* __restrict__ clw, float* __restrict__ out, int write_ids)
{
    const float p2 = g_cls[q*8+7];
    float d2 = fmaxf(g_v2[t] + p2 - 2.0f * best_ab, 0.0f) / 100.0f;
    const int lab = g_lab[t];
    float cls = g_cls[q*8+lab] + g_cls[q*8+4] + g_cls[q*8+5+clos];
    float C = d2 * clw[t] - cls;
    out[q * Tn + t] = C;
    if (write_ids) out[Qn * Tn + q * Tn + t] = (float)ids;
}

// ---------------------------------------------------------------------------
// HMMA kernel: one CTA = (closed t, dir, 128-q tile). 8 warps = 4(M) x 2(N).
#define BPITCH 144
__global__ void __launch_bounds__(256, 2)
mma_kernel(int write_ids)
{
    __shared__ unsigned ssph[648], sspl[648];
    __shared__ char sB[2][128 * BPITCH];
    __shared__ float redv[4][128];
    __shared__ int   redi[4][128];
    __shared__ float redv2[4][128];

    const int tid  = threadIdx.x;
    const int wid  = tid >> 5, lane = tid & 31;
    const int wm   = wid & 3,  wn = wid >> 2;
    const int t    = g_tperm[blockIdx.x];
    if (!g_clo[t]) return;
    const int dir  = blockIdx.y >> 3;
    const int q0   = (blockIdx.y & 7) * 128;
    const int m0   = wm * 32;
    const int n0   = wn * 64;
    const int g    = lane >> 2;
    const int t2   = (lane & 3) * 2;

    {
        const unsigned* gh = g_sp_hi + (dir * Tn + t) * 648;
        const unsigned* gl = g_sp_lo + (dir * Tn + t) * 648;
        for (int j = tid; j < 648; j += 256) { ssph[j] = gh[j]; sspl[j] = gl[j]; }
    }

    float c[2][8][4];
    #pragma unroll
    for (int mt = 0; mt < 2; mt++)
        #pragma unroll
        for (int nt = 0; nt < 8; nt++)
            #pragma unroll
            for (int r = 0; r < 4; r++) c[mt][nt][r] = 0.f;

    int off0[2], off1[2];
    bool val0[2], val1[2];
    #pragma unroll
    for (int mt = 0; mt < 2; mt++) {
        int v0 = m0 + mt * 16 + g;
        val0[mt] = (v0 < 100);
        val1[mt] = (v0 + 8 < 100);
        off0[mt] = val0[mt] ? 3 * (100 - v0) : 0;
        off1[mt] = val1[mt] ? 3 * (100 - v0) - 24 : 0;
    }

    for (int kc = 0; kc < 5; kc++) {
        __syncthreads();
        #pragma unroll
        for (int plane = 0; plane < 2; plane++) {
            const __nv_bfloat16* src = (plane ? g_pb_lo : g_pb_hi);
            for (int i = tid; i < 128 * 16; i += 256) {
                int row = i >> 4, w = i & 15;
                u64 v = *(const u64*)(src + (u64)(q0 + row) * KP + kc * 64 + w * 4);
                *(u64*)(sB[plane] + row * BPITCH + w * 8) = v;
            }
        }
        __syncthreads();

        #pragma unroll
        for (int ks = 0; ks < 4; ks++) {
            const int kk = kc * 64 + ks * 16 + t2;
            unsigned ah[2][4], al[2][4];
            #pragma unroll
            for (int mt = 0; mt < 2; mt++) {
                ah[mt][0] = val0[mt] ? ssph[off0[mt] + kk]     : 0u;
                ah[mt][1] = val1[mt] ? ssph[off1[mt] + kk]     : 0u;
                ah[mt][2] = val0[mt] ? ssph[off0[mt] + kk + 8] : 0u;
                ah[mt][3] = val1[mt] ? ssph[off1[mt] + kk + 8] : 0u;
                al[mt][0] = val0[mt] ? sspl[off0[mt] + kk]     : 0u;
                al[mt][1] = val1[mt] ? sspl[off1[mt] + kk]     : 0u;
                al[mt][2] = val0[mt] ? sspl[off0[mt] + kk + 8] : 0u;
                al[mt][3] = val1[mt] ? sspl[off1[mt] + kk + 8] : 0u;
            }
            #pragma unroll
            for (int nt = 0; nt < 8; nt++) {
                const int brow = n0 + nt * 8 + g;
                const char* bh = sB[0] + brow * BPITCH + (ks * 16 + t2) * 2;
                const char* bl = sB[1] + brow * BPITCH + (ks * 16 + t2) * 2;
                unsigned bh0 = *(const unsigned*)bh;
                unsigned bh1 = *(const unsigned*)(bh + 16);
                unsigned bl0 = *(const unsigned*)bl;
                unsigned bl1 = *(const unsigned*)(bl + 16);
                #pragma unroll
                for (int mt = 0; mt < 2; mt++) {
                    mma16816(c[mt][nt], ah[mt], bh0, bh1);
                    mma16816(c[mt][nt], al[mt], bh0, bh1);
                    mma16816(c[mt][nt], ah[mt], bl0, bl1);
                }
            }
        }
    }

    // ---- epilogue: top-2 argmax over v per q column ----
    const float NINF = -__int_as_float(0x7f800000);
    #pragma unroll
    for (int nt = 0; nt < 8; nt++) {
        #pragma unroll
        for (int cp = 0; cp < 2; cp++) {
            float bv = NINF; int bx = 127; float bv2 = NINF;
            #pragma unroll
            for (int mt = 0; mt < 2; mt++) {
                #pragma unroll
                for (int rh = 0; rh < 2; rh++) {
                    int v = m0 + mt * 16 + rh * 8 + g;
                    float val = (v < 100) ? c[mt][nt][rh * 2 + cp] : NINF;
                    top2_merge(bv, bx, bv2, val, v, NINF);
                }
            }
            #pragma unroll
            for (int m = 4; m <= 16; m <<= 1) {
                float ov  = __shfl_xor_sync(0xffffffffu, bv, m);
                int   ox  = __shfl_xor_sync(0xffffffffu, bx, m);
                float ov2 = __shfl_xor_sync(0xffffffffu, bv2, m);
                top2_merge(bv, bx, bv2, ov, ox, ov2);
            }
            if (lane < 4) {
                int col = n0 + nt * 8 + t2 + cp;
                redv[wm][col]  = bv;
                redi[wm][col]  = bx;
                redv2[wm][col] = bv2;
            }
        }
    }
    __syncthreads();
    if (tid < 128) {
        int col = tid;
        float bv = redv[0][col]; int bx = redi[0][col]; float bv2 = redv2[0][col];
        #pragma unroll
        for (int w = 1; w < 4; w++)
            top2_merge(bv, bx, bv2, redv[w][col], redi[w][col], redv2[w][col]);
        int o = (dir * Tn + t) * Qn + q0 + col;
        g_pab[o] = bv; g_pix[o] = bx; g_pv2[o] = bv2;
    }
}

// ---------------------------------------------------------------------------
__global__ void combine_kernel(const float* __restrict__ clw,
                               float* __restrict__ out, int write_ids)
{
    int idx = blockIdx.x * 256 + threadIdx.x;
    int t = idx >> 10, q = idx & 1023;
    if (!g_clo[t]) return;
    float f1 = g_pab[t * Qn + q];        int xf = g_pix[t * Qn + q];
    float f2 = g_pv2[t * Qn + q];
    float w1 = g_pab[(Tn + t) * Qn + q]; int xb = g_pix[(Tn + t) * Qn + q];
    float w2 = g_pv2[(Tn + t) * Qn + q];
    float best, second; int ids;
    if (w1 > f1) { best = w1; ids = 99 - xb; second = fmaxf(f1, w2); }
    else         { best = f1; ids = xf;      second = fmaxf(w1, f2); }
    epilogue_write(best, ids, t, q, 1, clw, out, write_ids);
    if (best - second < EPSGAP) {
        int slot = atomicAdd(&g_fcnt, 1);
        g_flist[slot] = (t << 10) | q;
    }
}

// ---------------------------------------------------------------------------
// exact fp32 rescue: one warp per ambiguous (t,q), all 200 variants
__global__ void __launch_bounds__(256)
rescue_kernel(const float* __restrict__ pred, const float* __restrict__ tgt,
              const float* __restrict__ clw, float* __restrict__ out, int write_ids)
{
    const int lane = threadIdx.x & 31;
    const int gw   = (blockIdx.x * 256 + threadIdx.x) >> 5;
    const int nw   = gridDim.x * 8;
    const int n    = g_fcnt;
    const float NINF = -__int_as_float(0x7f800000);
    for (int i = gw; i < n; i += nw) {
        int code = g_flist[i];
        int t = code >> 10, q = code & 1023;
        const float* tg = tgt + t * Kn;
        const float* pq = pred + q * Kn;
        float bv = NINF; int bx = 255;
        for (int r = lane; r < 200; r += 32) {
            int  sh  = (r < 100) ? (100 - r) : (200 - r);
            bool rev = (r >= 100);
            float c0 = 0.f, c1 = 0.f, c2 = 0.f;
            for (int j = 0; j < 100; j++) {
                int jj = j + sh; if (jj >= 100) jj -= 100;
                int row = rev ? (99 - jj) : jj;
                c0 = fmaf(pq[j*3+0], tg[row*3+0], c0);
                c1 = fmaf(pq[j*3+1], tg[row*3+1], c1);
                c2 = fmaf(pq[j*3+2], tg[row*3+2], c2);
            }
            float ab = c0 + c1 + c2;
            if (ab > bv) { bv = ab; bx = r; }
        }
        #pragma unroll
        for (int m = 16; m >= 1; m >>= 1) {
            float ov = __shfl_xor_sync(0xffffffffu, bv, m);
            int   ox = __shfl_xor_sync(0xffffffffu, bx, m);
            if (ov > bv || (ov == bv && ox < bx)) { bv = ov; bx = ox; }
        }
        if (lane == 0) {
            int ids = (bx < 100) ? bx : 199 - bx;
            epilogue_write(bv, ids, t, q, 1, clw, out, write_ids);
        }
    }
}

// ---------------------------------------------------------------------------
// open curves: k-pair transposed loads (LDG.64, batched MLP=6), ffma2 math
__global__ void __launch_bounds__(256, 4)
light_kernel(const float* __restrict__ tgt,
             const float* __restrict__ clw, float* __restrict__ out, int write_ids)
{
    __shared__ float2 sfp[152], sbp[152];
    const int t = blockIdx.x;
    if (g_clo[t]) return;
    const int q = blockIdx.y * 256 + threadIdx.x;
    const float* tg = tgt + t * Kn;
    for (int j = threadIdx.x; j < 150; j += 256) {
        int idx = 300 + 2 * j;
        sfp[j] = make_float2(sext_fwd(tg, idx), sext_fwd(tg, idx + 1));
        sbp[j] = make_float2(sext_bwd(tg, idx), sext_bwd(tg, idx + 1));
    }
    __syncthreads();
    const u64* p2  = (const u64*)g_predT2;
    const u64* suf = (const u64*)sfp;
    const u64* sub = (const u64*)sbp;
    u64 af0 = 0ull, af1 = 0ull, ab0 = 0ull, ab1 = 0ull;
    #pragma unroll 1
    for (int i0 = 0; i0 < 150; i0 += 6) {
        u64 p[6];
        #pragma unroll
        for (int j = 0; j < 6; j++)
            p[j] = p2[(i0 + j) * Qn + q];
        #pragma unroll
        for (int j = 0; j < 6; j++) {
            if (j & 1) { ffma2(af1, p[j], suf[i0 + j]); ffma2(ab1, p[j], sub[i0 + j]); }
            else       { ffma2(af0, p[j], suf[i0 + j]); ffma2(ab0, p[j], sub[i0 + j]); }
        }
    }
    float af = pairsum(af0) + pairsum(af1);
    float ab = pairsum(ab0) + pairsum(ab1);
    epilogue_write(fmaxf(af, ab), 0, t, q, 0, clw, out, write_ids);
}

// ---------------------------------------------------------------------------
extern "C" void kernel_launch(void* const* d_in, const int* in_sizes, int n_in,
                              void* d_out, int out_size)
{
    const float* pred = (const float*)d_in[0];
    const float* vlog = (const float*)d_in[1];
    const float* tlog = (const float*)d_in[2];
    const float* clog = (const float*)d_in[3];
    const float* tgt  = (const float*)d_in[4];
    const int*   lab  = (const int*)d_in[5];
    const int*   clo  = (const int*)d_in[6];
    const float* clw  = (const float*)d_in[7];
    float* out = (float*)d_out;

    const int write_ids = (out_size >= 2 * Qn * Tn) ? 1 : 0;

    pre_kernel<<<165, 256>>>(pred, vlog, tlog, clog, tgt, lab, clo);
    pre2_kernel<<<2576 + 600, 256>>>(pred, tgt);
    mma_kernel<<<dim3(Tn, 16), 256>>>(write_ids);
    light_kernel<<<dim3(Tn, 4), 256>>>(tgt, clw, out, write_ids);
    combine_kernel<<<1024, 256>>>(clw, out, write_ids);
    rescue_kernel<<<512, 256>>>(pred, tgt, clw, out, write_ids);
}

// round 13
// speedup vs baseline: 2.4486x; 1.2429x over previous
#include <cuda_runtime.h>
#include <cuda_fp16.h>
#include <math.h>

#define Qn 1024
#define Tn 256
#define Nn 100
#define Kn 300
#define KP 320          // padded K (5 chunks of 64)
#define EPSGAP 0.05f    // fp16-path ambiguity threshold for exact rescue

typedef unsigned long long u64;

__device__ float g_cls[Qn * 8];
__device__ float g_v2[Tn];
__device__ int   g_lab[Tn];
__device__ int   g_clo[Tn];
__device__ int   g_tperm[Tn];
__device__ __half g_pb[Qn * KP];             // pred fp16 plane, [q][KP]
__device__ unsigned g_sp_hi[2 * Tn * 648];   // extended-target pair table (fp16x2), hi
__device__ unsigned g_sp_lo[2 * Tn * 648];   // residual pairs
__device__ float2 g_predT2[150 * Qn];        // transposed pred k-pairs [kp][q]
__device__ float g_pab[2 * Tn * Qn];         // per-(dir,t,q) best ab
__device__ int   g_pix[2 * Tn * Qn];         // its v index
__device__ float g_pv2[2 * Tn * Qn];         // runner-up ab
__device__ int   g_flist[Tn * Qn];           // flagged (t<<10|q)
__device__ int   g_fcnt;

__device__ __forceinline__ void ffma2(u64& c, u64 a, u64 b) {
    asm("fma.rn.f32x2 %0, %1, %2, %3;" : "=l"(c) : "l"(a), "l"(b), "l"(c));
}
__device__ __forceinline__ float pairsum(u64 v) {
    return __uint_as_float((unsigned)v) + __uint_as_float((unsigned)(v >> 32));
}
__device__ __forceinline__ void mma16816h(float* c, const unsigned* a, unsigned b0, unsigned b1) {
    asm volatile(
        "mma.sync.aligned.m16n8k16.row.col.f32.f16.f16.f32 "
        "{%0,%1,%2,%3}, {%4,%5,%6,%7}, {%8,%9}, {%0,%1,%2,%3};"
        : "+f"(c[0]), "+f"(c[1]), "+f"(c[2]), "+f"(c[3])
        : "r"(a[0]), "r"(a[1]), "r"(a[2]), "r"(a[3]), "r"(b0), "r"(b1));
}
__device__ __forceinline__ void top2_merge(float& v1, int& x1, float& v2,
                                           float ov1, int ox1, float ov2) {
    float lo = fminf(v1, ov1);
    if (ov1 > v1)               { v1 = ov1; x1 = ox1; }
    else if (ov1 == v1 && ox1 < x1) x1 = ox1;
    v2 = fmaxf(v2, fmaxf(lo, ov2));
}

// ---------------------------------------------------------------------------
__device__ __forceinline__ float sext_fwd(const float* __restrict__ tg, int idx) {
    int m = idx / 3, c = idx - m * 3;
    int mm = (m >= Nn) ? (m - Nn) : m;
    return tg[mm * 3 + c];
}
__device__ __forceinline__ float sext_bwd(const float* __restrict__ tg, int idx) {
    int m = idx / 3, c = idx - m * 3;
    int mm = (m >= Nn) ? (m - Nn) : m;
    return tg[(Nn - 1 - mm) * 3 + c];
}

// ---------------------------------------------------------------------------
// pre: blocks 0..3 softmax; 4..131 p2 (warp/q); 132..163 v2 (warp/t); 164 labels+perm
__global__ void pre_kernel(const float* __restrict__ pred,
                           const float* __restrict__ vlog,
                           const float* __restrict__ tlog,
                           const float* __restrict__ clog,
                           const float* __restrict__ tgt,
                           const int* __restrict__ lab32,
                           const int* __restrict__ clo32)
{
    const int tid = threadIdx.x;
    const int bx  = blockIdx.x;
    if (bx < 4) {
        const int q = bx * 256 + tid;
        float x0 = tlog[q*4+0], x1 = tlog[q*4+1], x2 = tlog[q*4+2], x3 = tlog[q*4+3];
        float m  = fmaxf(fmaxf(x0, x1), fmaxf(x2, x3));
        float e0 = expf(x0-m), e1 = expf(x1-m), e2 = expf(x2-m), e3 = expf(x3-m);
        float s  = e0 + e1 + e2 + e3;
        g_cls[q*8+0] = logf(e0/s + 1e-6f);
        g_cls[q*8+1] = logf(e1/s + 1e-6f);
        g_cls[q*8+2] = logf(e2/s + 1e-6f);
        g_cls[q*8+3] = logf(e3/s + 1e-6f);
        float a0 = vlog[q*2+0], a1 = vlog[q*2+1];
        float ma = fmaxf(a0, a1);
        float f0 = expf(a0-ma), f1 = expf(a1-ma);
        g_cls[q*8+4] = logf(f0/(f0+f1) + 1e-6f);
        float b0 = clog[q*2+0], b1 = clog[q*2+1];
        float mb = fmaxf(b0, b1);
        float h0 = expf(b0-mb), h1 = expf(b1-mb);
        float hs = h0 + h1;
        g_cls[q*8+5] = logf(h0/hs + 1e-6f);
        g_cls[q*8+6] = logf(h1/hs + 1e-6f);
    } else if (bx < 132) {
        const int q    = (bx - 4) * 8 + (tid >> 5);
        const int lane = tid & 31;
        const float* p = pred + q * Kn;
        float s = 0.f;
        #pragma unroll
        for (int j = 0; j < 10; j++) {
            int k = lane + 32 * j;
            if (k < Kn) { float v = p[k]; s = fmaf(v, v, s); }
        }
        #pragma unroll
        for (int m = 16; m >= 1; m >>= 1) s += __shfl_xor_sync(0xffffffffu, s, m);
        if (lane == 0) g_cls[q*8+7] = s;
    } else if (bx < 164) {
        const int t    = (bx - 132) * 8 + (tid >> 5);
        const int lane = tid & 31;
        const float* p = tgt + t * Kn;
        float s = 0.f;
        #pragma unroll
        for (int j = 0; j < 10; j++) {
            int k = lane + 32 * j;
            if (k < Kn) { float v = p[k]; s = fmaf(v, v, s); }
        }
        #pragma unroll
        for (int m = 16; m >= 1; m >>= 1) s += __shfl_xor_sync(0xffffffffu, s, m);
        if (lane == 0) g_v2[t] = s;
    } else {
        if (tid == 0) g_fcnt = 0;   // reset rescue list each launch (graph replays)
        __shared__ int flag;
        if (tid == 0) flag = 0;
        __syncthreads();
        if (tid < 128) {
            if (lab32[2*tid+1] != 0 || clo32[2*tid+1] != 0) atomicOr(&flag, 1);
        }
        __syncthreads();
        const int t = tid;
        int lv, cv;
        if (flag) { lv = lab32[t]; cv = clo32[t]; }
        else {
            lv = (int)((const long long*)lab32)[t];
            cv = (int)((const long long*)clo32)[t];
        }
        g_lab[t] = lv;
        g_clo[t] = cv;
        __syncthreads();
        if (tid == 0) {
            int a = 0, b = 0;
            for (int i = 0; i < Tn; i++) if (g_clo[i]) g_tperm[a++] = i;
            for (int i = 0; i < Tn; i++) if (!g_clo[i]) g_tperm[a + (b++)] = i;
        }
    }
}

// fp16 plane for preds, fp16 hi/lo target pair tables, pred k-pair transpose
__global__ void pre2_kernel(const float* __restrict__ pred,
                            const float* __restrict__ tgt)
{
    int idx = blockIdx.x * 256 + threadIdx.x;
    if (blockIdx.x < 1280) {
        int q = idx / KP, k = idx - q * KP;
        float x = (k < Kn) ? pred[q * Kn + k] : 0.f;
        g_pb[idx] = __float2half_rn(x);
    } else if (blockIdx.x < 2576) {
        int i2 = idx - 1280 * 256;
        if (i2 >= 2 * Tn * 648) return;
        int dt = i2 / 648, j = i2 - dt * 648;
        int dir = dt >> 8, t = dt & 255;
        const float* tg = tgt + t * Kn;
        float x0 = 0.f, x1 = 0.f;
        if (j < 600)     x0 = dir ? sext_bwd(tg, j)     : sext_fwd(tg, j);
        if (j + 1 < 600) x1 = dir ? sext_bwd(tg, j + 1) : sext_fwd(tg, j + 1);
        __half h0 = __float2half_rn(x0), h1 = __float2half_rn(x1);
        __half l0 = __float2half_rn(x0 - __half2float(h0));
        __half l1 = __float2half_rn(x1 - __half2float(h1));
        g_sp_hi[i2] = (unsigned)__half_as_ushort(h0) | ((unsigned)__half_as_ushort(h1) << 16);
        g_sp_lo[i2] = (unsigned)__half_as_ushort(l0) | ((unsigned)__half_as_ushort(l1) << 16);
    } else {
        int i3 = idx - 2576 * 256;           // 0 .. 153599
        if (i3 >= 150 * Qn) return;
        int q = i3 / 150, kp = i3 - q * 150;
        const float2 v = *(const float2*)(pred + q * Kn + 2 * kp);
        g_predT2[kp * Qn + q] = v;
    }
}

// ---------------------------------------------------------------------------
__device__ __forceinline__ void epilogue_write(
    float best_ab, int ids, int t, int q, int clos,
    const float* __restrict__ clw, float* __restrict__ out, int write_ids)
{
    const float p2 = g_cls[q*8+7];
    float d2 = fmaxf(g_v2[t] + p2 - 2.0f * best_ab, 0.0f) / 100.0f;
    const int lab = g_lab[t];
    float cls = g_cls[q*8+lab] + g_cls[q*8+4] + g_cls[q*8+5+clos];
    float C = d2 * clw[t] - cls;
    out[q * Tn + t] = C;
    if (write_ids) out[Qn * Tn + q * Tn + t] = (float)ids;
}

// ---------------------------------------------------------------------------
// HMMA kernel: one CTA = (closed t, dir, 128-q tile). 8 warps = 4(M) x 2(N).
// fp16 2-term: D = Ah*B + Al*B. B single fp16 plane.
#define BPITCH 144
__global__ void __launch_bounds__(256, 2)
mma_kernel(int write_ids)
{
    __shared__ unsigned ssph[648], sspl[648];
    __shared__ char sB[128 * BPITCH];
    __shared__ float redv[4][128];
    __shared__ int   redi[4][128];
    __shared__ float redv2[4][128];

    const int tid  = threadIdx.x;
    const int wid  = tid >> 5, lane = tid & 31;
    const int wm   = wid & 3,  wn = wid >> 2;
    const int t    = g_tperm[blockIdx.x];
    if (!g_clo[t]) return;
    const int dir  = blockIdx.y >> 3;
    const int q0   = (blockIdx.y & 7) * 128;
    const int m0   = wm * 32;
    const int n0   = wn * 64;
    const int g    = lane >> 2;
    const int t2   = (lane & 3) * 2;

    {
        const unsigned* gh = g_sp_hi + (dir * Tn + t) * 648;
        const unsigned* gl = g_sp_lo + (dir * Tn + t) * 648;
        for (int j = tid; j < 648; j += 256) { ssph[j] = gh[j]; sspl[j] = gl[j]; }
    }

    float c[2][8][4];
    #pragma unroll
    for (int mt = 0; mt < 2; mt++)
        #pragma unroll
        for (int nt = 0; nt < 8; nt++)
            #pragma unroll
            for (int r = 0; r < 4; r++) c[mt][nt][r] = 0.f;

    int off0[2], off1[2];
    bool val0[2], val1[2], tilev[2];
    #pragma unroll
    for (int mt = 0; mt < 2; mt++) {
        int v0 = m0 + mt * 16 + g;
        val0[mt]  = (v0 < 100);
        val1[mt]  = (v0 + 8 < 100);
        tilev[mt] = (m0 + mt * 16 < 100);   // warp-uniform: whole m-tile invalid?
        off0[mt]  = val0[mt] ? 3 * (100 - v0) : 0;
        off1[mt]  = val1[mt] ? 3 * (100 - v0) - 24 : 0;
    }

    for (int kc = 0; kc < 5; kc++) {
        __syncthreads();
        // stage B chunk (single fp16 plane): rows q0..q0+127, k = kc*64..+64
        for (int i = tid; i < 128 * 16; i += 256) {
            int row = i >> 4, w = i & 15;
            u64 v = *(const u64*)(g_pb + (u64)(q0 + row) * KP + kc * 64 + w * 4);
            *(u64*)(sB + row * BPITCH + w * 8) = v;
        }
        __syncthreads();

        #pragma unroll
        for (int ks = 0; ks < 4; ks++) {
            const int kk = kc * 64 + ks * 16 + t2;
            unsigned ah[2][4], al[2][4];
            #pragma unroll
            for (int mt = 0; mt < 2; mt++) {
                ah[mt][0] = val0[mt] ? ssph[off0[mt] + kk]     : 0u;
                ah[mt][1] = val1[mt] ? ssph[off1[mt] + kk]     : 0u;
                ah[mt][2] = val0[mt] ? ssph[off0[mt] + kk + 8] : 0u;
                ah[mt][3] = val1[mt] ? ssph[off1[mt] + kk + 8] : 0u;
                al[mt][0] = val0[mt] ? sspl[off0[mt] + kk]     : 0u;
                al[mt][1] = val1[mt] ? sspl[off1[mt] + kk]     : 0u;
                al[mt][2] = val0[mt] ? sspl[off0[mt] + kk + 8] : 0u;
                al[mt][3] = val1[mt] ? sspl[off1[mt] + kk + 8] : 0u;
            }
            #pragma unroll
            for (int nt = 0; nt < 8; nt++) {
                const int brow = n0 + nt * 8 + g;
                const char* bp = sB + brow * BPITCH + (ks * 16 + t2) * 2;
                unsigned b0 = *(const unsigned*)bp;
                unsigned b1 = *(const unsigned*)(bp + 16);
                #pragma unroll
                for (int mt = 0; mt < 2; mt++) {
                    if (tilev[mt]) {
                        mma16816h(c[mt][nt], ah[mt], b0, b1);
                        mma16816h(c[mt][nt], al[mt], b0, b1);
                    }
                }
            }
        }
    }

    // ---- epilogue: top-2 argmax over v per q column ----
    const float NINF = -__int_as_float(0x7f800000);
    #pragma unroll
    for (int nt = 0; nt < 8; nt++) {
        #pragma unroll
        for (int cp = 0; cp < 2; cp++) {
            float bv = NINF; int bx = 127; float bv2 = NINF;
            #pragma unroll
            for (int mt = 0; mt < 2; mt++) {
                #pragma unroll
                for (int rh = 0; rh < 2; rh++) {
                    int v = m0 + mt * 16 + rh * 8 + g;
                    float val = (v < 100) ? c[mt][nt][rh * 2 + cp] : NINF;
                    top2_merge(bv, bx, bv2, val, v, NINF);
                }
            }
            #pragma unroll
            for (int m = 4; m <= 16; m <<= 1) {
                float ov  = __shfl_xor_sync(0xffffffffu, bv, m);
                int   ox  = __shfl_xor_sync(0xffffffffu, bx, m);
                float ov2 = __shfl_xor_sync(0xffffffffu, bv2, m);
                top2_merge(bv, bx, bv2, ov, ox, ov2);
            }
            if (lane < 4) {
                int col = n0 + nt * 8 + t2 + cp;
                redv[wm][col]  = bv;
                redi[wm][col]  = bx;
                redv2[wm][col] = bv2;
            }
        }
    }
    __syncthreads();
    if (tid < 128) {
        int col = tid;
        float bv = redv[0][col]; int bx = redi[0][col]; float bv2 = redv2[0][col];
        #pragma unroll
        for (int w = 1; w < 4; w++)
            top2_merge(bv, bx, bv2, redv[w][col], redi[w][col], redv2[w][col]);
        int o = (dir * Tn + t) * Qn + q0 + col;
        g_pab[o] = bv; g_pix[o] = bx; g_pv2[o] = bv2;
    }
}

// ---------------------------------------------------------------------------
__global__ void combine_kernel(const float* __restrict__ clw,
                               float* __restrict__ out, int write_ids)
{
    int idx = blockIdx.x * 256 + threadIdx.x;
    int t = idx >> 10, q = idx & 1023;
    if (!g_clo[t]) return;
    float f1 = g_pab[t * Qn + q];        int xf = g_pix[t * Qn + q];
    float f2 = g_pv2[t * Qn + q];
    float w1 = g_pab[(Tn + t) * Qn + q]; int xb = g_pix[(Tn + t) * Qn + q];
    float w2 = g_pv2[(Tn + t) * Qn + q];
    float best, second; int ids;
    if (w1 > f1) { best = w1; ids = 99 - xb; second = fmaxf(f1, w2); }
    else         { best = f1; ids = xf;      second = fmaxf(w1, f2); }
    epilogue_write(best, ids, t, q, 1, clw, out, write_ids);
    if (best - second < EPSGAP) {
        int slot = atomicAdd(&g_fcnt, 1);
        g_flist[slot] = (t << 10) | q;
    }
}

// ---------------------------------------------------------------------------
// exact fp32 rescue: one warp per ambiguous (t,q), all 200 variants
__global__ void __launch_bounds__(256)
rescue_kernel(const float* __restrict__ pred, const float* __restrict__ tgt,
              const float* __restrict__ clw, float* __restrict__ out, int write_ids)
{
    const int lane = threadIdx.x & 31;
    const int gw   = (blockIdx.x * 256 + threadIdx.x) >> 5;
    const int nw   = gridDim.x * 8;
    const int n    = g_fcnt;
    const float NINF = -__int_as_float(0x7f800000);
    for (int i = gw; i < n; i += nw) {
        int code = g_flist[i];
        int t = code >> 10, q = code & 1023;
        const float* tg = tgt + t * Kn;
        const float* pq = pred + q * Kn;
        float bv = NINF; int bx = 255;
        for (int r = lane; r < 200; r += 32) {
            int  sh  = (r < 100) ? (100 - r) : (200 - r);
            bool rev = (r >= 100);
            float c0 = 0.f, c1 = 0.f, c2 = 0.f;
            for (int j = 0; j < 100; j++) {
                int jj = j + sh; if (jj >= 100) jj -= 100;
                int row = rev ? (99 - jj) : jj;
                c0 = fmaf(pq[j*3+0], tg[row*3+0], c0);
                c1 = fmaf(pq[j*3+1], tg[row*3+1], c1);
                c2 = fmaf(pq[j*3+2], tg[row*3+2], c2);
            }
            float ab = c0 + c1 + c2;
            if (ab > bv) { bv = ab; bx = r; }
        }
        #pragma unroll
        for (int m = 16; m >= 1; m >>= 1) {
            float ov = __shfl_xor_sync(0xffffffffu, bv, m);
            int   ox = __shfl_xor_sync(0xffffffffu, bx, m);
            if (ov > bv || (ov == bv && ox < bx)) { bv = ov; bx = ox; }
        }
        if (lane == 0) {
            int ids = (bx < 100) ? bx : 199 - bx;
            epilogue_write(bv, ids, t, q, 1, clw, out, write_ids);
        }
    }
}

// ---------------------------------------------------------------------------
// open curves: k-pair transposed loads (LDG.64, batched MLP=6), ffma2 math
__global__ void __launch_bounds__(256, 4)
light_kernel(const float* __restrict__ tgt,
             const float* __restrict__ clw, float* __restrict__ out, int write_ids)
{
    __shared__ float2 sfp[152], sbp[152];
    const int t = blockIdx.x;
    if (g_clo[t]) return;
    const int q = blockIdx.y * 256 + threadIdx.x;
    const float* tg = tgt + t * Kn;
    for (int j = threadIdx.x; j < 150; j += 256) {
        int idx = 300 + 2 * j;
        sfp[j] = make_float2(sext_fwd(tg, idx), sext_fwd(tg, idx + 1));
        sbp[j] = make_float2(sext_bwd(tg, idx), sext_bwd(tg, idx + 1));
    }
    __syncthreads();
    const u64* p2  = (const u64*)g_predT2;
    const u64* suf = (const u64*)sfp;
    const u64* sub = (const u64*)sbp;
    u64 af0 = 0ull, af1 = 0ull, ab0 = 0ull, ab1 = 0ull;
    #pragma unroll 1
    for (int i0 = 0; i0 < 150; i0 += 6) {
        u64 p[6];
        #pragma unroll
        for (int j = 0; j < 6; j++)
            p[j] = p2[(i0 + j) * Qn + q];
        #pragma unroll
        for (int j = 0; j < 6; j++) {
            if (j & 1) { ffma2(af1, p[j], suf[i0 + j]); ffma2(ab1, p[j], sub[i0 + j]); }
            else       { ffma2(af0, p[j], suf[i0 + j]); ffma2(ab0, p[j], sub[i0 + j]); }
        }
    }
    float af = pairsum(af0) + pairsum(af1);
    float ab = pairsum(ab0) + pairsum(ab1);
    epilogue_write(fmaxf(af, ab), 0, t, q, 0, clw, out, write_ids);
}

// ---------------------------------------------------------------------------
extern "C" void kernel_launch(void* const* d_in, const int* in_sizes, int n_in,
                              void* d_out, int out_size)
{
    const float* pred = (const float*)d_in[0];
    const float* vlog = (const float*)d_in[1];
    const float* tlog = (const float*)d_in[2];
    const float* clog = (const float*)d_in[3];
    const float* tgt  = (const float*)d_in[4];
    const int*   lab  = (const int*)d_in[5];
    const int*   clo  = (const int*)d_in[6];
    const float* clw  = (const float*)d_in[7];
    float* out = (float*)d_out;

    const int write_ids = (out_size >= 2 * Qn * Tn) ? 1 : 0;

    pre_kernel<<<165, 256>>>(pred, vlog, tlog, clog, tgt, lab, clo);
    pre2_kernel<<<2576 + 600, 256>>>(pred, tgt);
    mma_kernel<<<dim3(Tn, 16), 256>>>(write_ids);
    light_kernel<<<dim3(Tn, 4), 256>>>(tgt, clw, out, write_ids);
    combine_kernel<<<1024, 256>>>(clw, out, write_ids);
    rescue_kernel<<<512, 256>>>(pred, tgt, clw, out, write_ids);
}

// round 14
// speedup vs baseline: 2.6459x; 1.0806x over previous
#include <cuda_runtime.h>
#include <cuda_fp16.h>
#include <math.h>

#define Qn 1024
#define Tn 256
#define Nn 100
#define Kn 300
#define KP 320          // padded K (5 chunks of 64)
#define EPSGAP 0.06f    // fp16 1-term ambiguity threshold (~5 sigma) for exact rescue

typedef unsigned long long u64;

__device__ float g_cls[Qn * 8];
__device__ float g_v2[Tn];
__device__ int   g_lab[Tn];
__device__ int   g_clo[Tn];
__device__ int   g_tperm[Tn];
__device__ __half g_pb[Qn * KP];             // pred fp16 plane, [q][KP]
__device__ unsigned g_sp[2 * Tn * 648];      // extended-target pair table (fp16x2)
__device__ float2 g_predT2[150 * Qn];        // transposed pred k-pairs [kp][q]
__device__ float g_pab[2 * Tn * Qn];         // per-(dir,t,q) best ab
__device__ int   g_pix[2 * Tn * Qn];         // its v index
__device__ float g_pv2[2 * Tn * Qn];         // runner-up ab
__device__ int   g_flist[Tn * Qn];           // flagged (t<<10|q)
__device__ int   g_fcnt;

__device__ __forceinline__ void ffma2(u64& c, u64 a, u64 b) {
    asm("fma.rn.f32x2 %0, %1, %2, %3;" : "=l"(c) : "l"(a), "l"(b), "l"(c));
}
__device__ __forceinline__ float pairsum(u64 v) {
    return __uint_as_float((unsigned)v) + __uint_as_float((unsigned)(v >> 32));
}
__device__ __forceinline__ void mma16816h(float* c, const unsigned* a, unsigned b0, unsigned b1) {
    asm volatile(
        "mma.sync.aligned.m16n8k16.row.col.f32.f16.f16.f32 "
        "{%0,%1,%2,%3}, {%4,%5,%6,%7}, {%8,%9}, {%0,%1,%2,%3};"
        : "+f"(c[0]), "+f"(c[1]), "+f"(c[2]), "+f"(c[3])
        : "r"(a[0]), "r"(a[1]), "r"(a[2]), "r"(a[3]), "r"(b0), "r"(b1));
}
__device__ __forceinline__ void top2_merge(float& v1, int& x1, float& v2,
                                           float ov1, int ox1, float ov2) {
    float lo = fminf(v1, ov1);
    if (ov1 > v1)               { v1 = ov1; x1 = ox1; }
    else if (ov1 == v1 && ox1 < x1) x1 = ox1;
    v2 = fmaxf(v2, fmaxf(lo, ov2));
}

// ---------------------------------------------------------------------------
__device__ __forceinline__ float sext_fwd(const float* __restrict__ tg, int idx) {
    int m = idx / 3, c = idx - m * 3;
    int mm = (m >= Nn) ? (m - Nn) : m;
    return tg[mm * 3 + c];
}
__device__ __forceinline__ float sext_bwd(const float* __restrict__ tg, int idx) {
    int m = idx / 3, c = idx - m * 3;
    int mm = (m >= Nn) ? (m - Nn) : m;
    return tg[(Nn - 1 - mm) * 3 + c];
}

// ---------------------------------------------------------------------------
// pre: blocks 0..3 softmax; 4..131 p2 (warp/q); 132..163 v2 (warp/t); 164 labels+perm
__global__ void pre_kernel(const float* __restrict__ pred,
                           const float* __restrict__ vlog,
                           const float* __restrict__ tlog,
                           const float* __restrict__ clog,
                           const float* __restrict__ tgt,
                           const int* __restrict__ lab32,
                           const int* __restrict__ clo32)
{
    const int tid = threadIdx.x;
    const int bx  = blockIdx.x;
    if (bx < 4) {
        const int q = bx * 256 + tid;
        float x0 = tlog[q*4+0], x1 = tlog[q*4+1], x2 = tlog[q*4+2], x3 = tlog[q*4+3];
        float m  = fmaxf(fmaxf(x0, x1), fmaxf(x2, x3));
        float e0 = expf(x0-m), e1 = expf(x1-m), e2 = expf(x2-m), e3 = expf(x3-m);
        float s  = e0 + e1 + e2 + e3;
        g_cls[q*8+0] = logf(e0/s + 1e-6f);
        g_cls[q*8+1] = logf(e1/s + 1e-6f);
        g_cls[q*8+2] = logf(e2/s + 1e-6f);
        g_cls[q*8+3] = logf(e3/s + 1e-6f);
        float a0 = vlog[q*2+0], a1 = vlog[q*2+1];
        float ma = fmaxf(a0, a1);
        float f0 = expf(a0-ma), f1 = expf(a1-ma);
        g_cls[q*8+4] = logf(f0/(f0+f1) + 1e-6f);
        float b0 = clog[q*2+0], b1 = clog[q*2+1];
        float mb = fmaxf(b0, b1);
        float h0 = expf(b0-mb), h1 = expf(b1-mb);
        float hs = h0 + h1;
        g_cls[q*8+5] = logf(h0/hs + 1e-6f);
        g_cls[q*8+6] = logf(h1/hs + 1e-6f);
    } else if (bx < 132) {
        const int q    = (bx - 4) * 8 + (tid >> 5);
        const int lane = tid & 31;
        const float* p = pred + q * Kn;
        float s = 0.f;
        #pragma unroll
        for (int j = 0; j < 10; j++) {
            int k = lane + 32 * j;
            if (k < Kn) { float v = p[k]; s = fmaf(v, v, s); }
        }
        #pragma unroll
        for (int m = 16; m >= 1; m >>= 1) s += __shfl_xor_sync(0xffffffffu, s, m);
        if (lane == 0) g_cls[q*8+7] = s;
    } else if (bx < 164) {
        const int t    = (bx - 132) * 8 + (tid >> 5);
        const int lane = tid & 31;
        const float* p = tgt + t * Kn;
        float s = 0.f;
        #pragma unroll
        for (int j = 0; j < 10; j++) {
            int k = lane + 32 * j;
            if (k < Kn) { float v = p[k]; s = fmaf(v, v, s); }
        }
        #pragma unroll
        for (int m = 16; m >= 1; m >>= 1) s += __shfl_xor_sync(0xffffffffu, s, m);
        if (lane == 0) g_v2[t] = s;
    } else {
        if (tid == 0) g_fcnt = 0;   // reset rescue list each launch (graph replays)
        __shared__ int flag;
        if (tid == 0) flag = 0;
        __syncthreads();
        if (tid < 128) {
            if (lab32[2*tid+1] != 0 || clo32[2*tid+1] != 0) atomicOr(&flag, 1);
        }
        __syncthreads();
        const int t = tid;
        int lv, cv;
        if (flag) { lv = lab32[t]; cv = clo32[t]; }
        else {
            lv = (int)((const long long*)lab32)[t];
            cv = (int)((const long long*)clo32)[t];
        }
        g_lab[t] = lv;
        g_clo[t] = cv;
        __syncthreads();
        if (tid == 0) {
            int a = 0, b = 0;
            for (int i = 0; i < Tn; i++) if (g_clo[i]) g_tperm[a++] = i;
            for (int i = 0; i < Tn; i++) if (!g_clo[i]) g_tperm[a + (b++)] = i;
        }
    }
}

// fp16 plane for preds, fp16 target pair tables, pred k-pair transpose
__global__ void pre2_kernel(const float* __restrict__ pred,
                            const float* __restrict__ tgt)
{
    int idx = blockIdx.x * 256 + threadIdx.x;
    if (blockIdx.x < 1280) {
        int q = idx / KP, k = idx - q * KP;
        float x = (k < Kn) ? pred[q * Kn + k] : 0.f;
        g_pb[idx] = __float2half_rn(x);
    } else if (blockIdx.x < 2576) {
        int i2 = idx - 1280 * 256;
        if (i2 >= 2 * Tn * 648) return;
        int dt = i2 / 648, j = i2 - dt * 648;
        int dir = dt >> 8, t = dt & 255;
        const float* tg = tgt + t * Kn;
        float x0 = 0.f, x1 = 0.f;
        if (j < 600)     x0 = dir ? sext_bwd(tg, j)     : sext_fwd(tg, j);
        if (j + 1 < 600) x1 = dir ? sext_bwd(tg, j + 1) : sext_fwd(tg, j + 1);
        __half h0 = __float2half_rn(x0), h1 = __float2half_rn(x1);
        g_sp[i2] = (unsigned)__half_as_ushort(h0) | ((unsigned)__half_as_ushort(h1) << 16);
    } else {
        int i3 = idx - 2576 * 256;           // 0 .. 153599
        if (i3 >= 150 * Qn) return;
        int q = i3 / 150, kp = i3 - q * 150;
        const float2 v = *(const float2*)(pred + q * Kn + 2 * kp);
        g_predT2[kp * Qn + q] = v;
    }
}

// ---------------------------------------------------------------------------
__device__ __forceinline__ void epilogue_write(
    float best_ab, int ids, int t, int q, int clos,
    const float* __restrict__ clw, float* __restrict__ out, int write_ids)
{
    const float p2 = g_cls[q*8+7];
    float d2 = fmaxf(g_v2[t] + p2 - 2.0f * best_ab, 0.0f) / 100.0f;
    const int lab = g_lab[t];
    float cls = g_cls[q*8+lab] + g_cls[q*8+4] + g_cls[q*8+5+clos];
    float C = d2 * clw[t] - cls;
    out[q * Tn + t] = C;
    if (write_ids) out[Qn * Tn + q * Tn + t] = (float)ids;
}

// ---------------------------------------------------------------------------
// HMMA kernel: one CTA = (closed t, dir, 128-q tile). 8 warps = 4(M) x 2(N).
// fp16 1-term: D = Ah*B (A fp16 target table, B fp16 pred plane).
#define BPITCH 144
__global__ void __launch_bounds__(256, 2)
mma_kernel(int write_ids)
{
    __shared__ unsigned ssp[648];
    __shared__ char sB[128 * BPITCH];
    __shared__ float redv[4][128];
    __shared__ int   redi[4][128];
    __shared__ float redv2[4][128];

    const int tid  = threadIdx.x;
    const int wid  = tid >> 5, lane = tid & 31;
    const int wm   = wid & 3,  wn = wid >> 2;
    const int t    = g_tperm[blockIdx.x];
    if (!g_clo[t]) return;
    const int dir  = blockIdx.y >> 3;
    const int q0   = (blockIdx.y & 7) * 128;
    const int m0   = wm * 32;
    const int n0   = wn * 64;
    const int g    = lane >> 2;
    const int t2   = (lane & 3) * 2;

    {
        const unsigned* gh = g_sp + (dir * Tn + t) * 648;
        for (int j = tid; j < 648; j += 256) ssp[j] = gh[j];
    }

    float c[2][8][4];
    #pragma unroll
    for (int mt = 0; mt < 2; mt++)
        #pragma unroll
        for (int nt = 0; nt < 8; nt++)
            #pragma unroll
            for (int r = 0; r < 4; r++) c[mt][nt][r] = 0.f;

    int off0[2], off1[2];
    bool val0[2], val1[2], tilev[2];
    #pragma unroll
    for (int mt = 0; mt < 2; mt++) {
        int v0 = m0 + mt * 16 + g;
        val0[mt]  = (v0 < 100);
        val1[mt]  = (v0 + 8 < 100);
        tilev[mt] = (m0 + mt * 16 < 100);   // warp-uniform: whole m-tile invalid?
        off0[mt]  = val0[mt] ? 3 * (100 - v0) : 0;
        off1[mt]  = val1[mt] ? 3 * (100 - v0) - 24 : 0;
    }

    for (int kc = 0; kc < 5; kc++) {
        __syncthreads();
        // stage B chunk (fp16 plane): rows q0..q0+127, k = kc*64..+64
        for (int i = tid; i < 128 * 16; i += 256) {
            int row = i >> 4, w = i & 15;
            u64 v = *(const u64*)(g_pb + (u64)(q0 + row) * KP + kc * 64 + w * 4);
            *(u64*)(sB + row * BPITCH + w * 8) = v;
        }
        __syncthreads();

        #pragma unroll
        for (int ks = 0; ks < 4; ks++) {
            const int kk = kc * 64 + ks * 16 + t2;
            unsigned ah[2][4];
            #pragma unroll
            for (int mt = 0; mt < 2; mt++) {
                ah[mt][0] = val0[mt] ? ssp[off0[mt] + kk]     : 0u;
                ah[mt][1] = val1[mt] ? ssp[off1[mt] + kk]     : 0u;
                ah[mt][2] = val0[mt] ? ssp[off0[mt] + kk + 8] : 0u;
                ah[mt][3] = val1[mt] ? ssp[off1[mt] + kk + 8] : 0u;
            }
            #pragma unroll
            for (int nt = 0; nt < 8; nt++) {
                const int brow = n0 + nt * 8 + g;
                const char* bp = sB + brow * BPITCH + (ks * 16 + t2) * 2;
                unsigned b0 = *(const unsigned*)bp;
                unsigned b1 = *(const unsigned*)(bp + 16);
                #pragma unroll
                for (int mt = 0; mt < 2; mt++)
                    if (tilev[mt]) mma16816h(c[mt][nt], ah[mt], b0, b1);
            }
        }
    }

    // ---- epilogue: top-2 argmax over v per q column ----
    const float NINF = -__int_as_float(0x7f800000);
    #pragma unroll
    for (int nt = 0; nt < 8; nt++) {
        #pragma unroll
        for (int cp = 0; cp < 2; cp++) {
            float bv = NINF; int bx = 127; float bv2 = NINF;
            #pragma unroll
            for (int mt = 0; mt < 2; mt++) {
                #pragma unroll
                for (int rh = 0; rh < 2; rh++) {
                    int v = m0 + mt * 16 + rh * 8 + g;
                    float val = (v < 100) ? c[mt][nt][rh * 2 + cp] : NINF;
                    top2_merge(bv, bx, bv2, val, v, NINF);
                }
            }
            #pragma unroll
            for (int m = 4; m <= 16; m <<= 1) {
                float ov  = __shfl_xor_sync(0xffffffffu, bv, m);
                int   ox  = __shfl_xor_sync(0xffffffffu, bx, m);
                float ov2 = __shfl_xor_sync(0xffffffffu, bv2, m);
                top2_merge(bv, bx, bv2, ov, ox, ov2);
            }
            if (lane < 4) {
                int col = n0 + nt * 8 + t2 + cp;
                redv[wm][col]  = bv;
                redi[wm][col]  = bx;
                redv2[wm][col] = bv2;
            }
        }
    }
    __syncthreads();
    if (tid < 128) {
        int col = tid;
        float bv = redv[0][col]; int bx = redi[0][col]; float bv2 = redv2[0][col];
        #pragma unroll
        for (int w = 1; w < 4; w++)
            top2_merge(bv, bx, bv2, redv[w][col], redi[w][col], redv2[w][col]);
        int o = (dir * Tn + t) * Qn + q0 + col;
        g_pab[o] = bv; g_pix[o] = bx; g_pv2[o] = bv2;
    }
}

// ---------------------------------------------------------------------------
__global__ void combine_kernel(const float* __restrict__ clw,
                               float* __restrict__ out, int write_ids)
{
    int idx = blockIdx.x * 256 + threadIdx.x;
    int t = idx >> 10, q = idx & 1023;
    if (!g_clo[t]) return;
    float f1 = g_pab[t * Qn + q];        int xf = g_pix[t * Qn + q];
    float f2 = g_pv2[t * Qn + q];
    float w1 = g_pab[(Tn + t) * Qn + q]; int xb = g_pix[(Tn + t) * Qn + q];
    float w2 = g_pv2[(Tn + t) * Qn + q];
    float best, second; int ids;
    if (w1 > f1) { best = w1; ids = 99 - xb; second = fmaxf(f1, w2); }
    else         { best = f1; ids = xf;      second = fmaxf(w1, f2); }
    epilogue_write(best, ids, t, q, 1, clw, out, write_ids);
    if (best - second < EPSGAP) {
        int slot = atomicAdd(&g_fcnt, 1);
        g_flist[slot] = (t << 10) | q;
    }
}

// ---------------------------------------------------------------------------
// exact fp32 rescue: one warp per ambiguous (t,q), all 200 variants
__global__ void __launch_bounds__(256)
rescue_kernel(const float* __restrict__ pred, const float* __restrict__ tgt,
              const float* __restrict__ clw, float* __restrict__ out, int write_ids)
{
    const int lane = threadIdx.x & 31;
    const int gw   = (blockIdx.x * 256 + threadIdx.x) >> 5;
    const int nw   = gridDim.x * 8;
    const int n    = g_fcnt;
    const float NINF = -__int_as_float(0x7f800000);
    for (int i = gw; i < n; i += nw) {
        int code = g_flist[i];
        int t = code >> 10, q = code & 1023;
        const float* tg = tgt + t * Kn;
        const float* pq = pred + q * Kn;
        float bv = NINF; int bx = 255;
        for (int r = lane; r < 200; r += 32) {
            int  sh  = (r < 100) ? (100 - r) : (200 - r);
            bool rev = (r >= 100);
            float c0 = 0.f, c1 = 0.f, c2 = 0.f;
            for (int j = 0; j < 100; j++) {
                int jj = j + sh; if (jj >= 100) jj -= 100;
                int row = rev ? (99 - jj) : jj;
                c0 = fmaf(pq[j*3+0], tg[row*3+0], c0);
                c1 = fmaf(pq[j*3+1], tg[row*3+1], c1);
                c2 = fmaf(pq[j*3+2], tg[row*3+2], c2);
            }
            float ab = c0 + c1 + c2;
            if (ab > bv) { bv = ab; bx = r; }
        }
        #pragma unroll
        for (int m = 16; m >= 1; m >>= 1) {
            float ov = __shfl_xor_sync(0xffffffffu, bv, m);
            int   ox = __shfl_xor_sync(0xffffffffu, bx, m);
            if (ov > bv || (ov == bv && ox < bx)) { bv = ov; bx = ox; }
        }
        if (lane == 0) {
            int ids = (bx < 100) ? bx : 199 - bx;
            epilogue_write(bv, ids, t, q, 1, clw, out, write_ids);
        }
    }
}

// ---------------------------------------------------------------------------
// open curves: k-pair transposed loads (LDG.64, batched MLP=6), ffma2 math
__global__ void __launch_bounds__(256, 4)
light_kernel(const float* __restrict__ tgt,
             const float* __restrict__ clw, float* __restrict__ out, int write_ids)
{
    __shared__ float2 sfp[152], sbp[152];
    const int t = blockIdx.x;
    if (g_clo[t]) return;
    const int q = blockIdx.y * 256 + threadIdx.x;
    const float* tg = tgt + t * Kn;
    for (int j = threadIdx.x; j < 150; j += 256) {
        int idx = 300 + 2 * j;
        sfp[j] = make_float2(sext_fwd(tg, idx), sext_fwd(tg, idx + 1));
        sbp[j] = make_float2(sext_bwd(tg, idx), sext_bwd(tg, idx + 1));
    }
    __syncthreads();
    const u64* p2  = (const u64*)g_predT2;
    const u64* suf = (const u64*)sfp;
    const u64* sub = (const u64*)sbp;
    u64 af0 = 0ull, af1 = 0ull, ab0 = 0ull, ab1 = 0ull;
    #pragma unroll 1
    for (int i0 = 0; i0 < 150; i0 += 6) {
        u64 p[6];
        #pragma unroll
        for (int j = 0; j < 6; j++)
            p[j] = p2[(i0 + j) * Qn + q];
        #pragma unroll
        for (int j = 0; j < 6; j++) {
            if (j & 1) { ffma2(af1, p[j], suf[i0 + j]); ffma2(ab1, p[j], sub[i0 + j]); }
            else       { ffma2(af0, p[j], suf[i0 + j]); ffma2(ab0, p[j], sub[i0 + j]); }
        }
    }
    float af = pairsum(af0) + pairsum(af1);
    float ab = pairsum(ab0) + pairsum(ab1);
    epilogue_write(fmaxf(af, ab), 0, t, q, 0, clw, out, write_ids);
}

// ---------------------------------------------------------------------------
extern "C" void kernel_launch(void* const* d_in, const int* in_sizes, int n_in,
                              void* d_out, int out_size)
{
    const float* pred = (const float*)d_in[0];
    const float* vlog = (const float*)d_in[1];
    const float* tlog = (const float*)d_in[2];
    const float* clog = (const float*)d_in[3];
    const float* tgt  = (const float*)d_in[4];
    const int*   lab  = (const int*)d_in[5];
    const int*   clo  = (const int*)d_in[6];
    const float* clw  = (const float*)d_in[7];
    float* out = (float*)d_out;

    const int write_ids = (out_size >= 2 * Qn * Tn) ? 1 : 0;

    pre_kernel<<<165, 256>>>(pred, vlog, tlog, clog, tgt, lab, clo);
    pre2_kernel<<<2576 + 600, 256>>>(pred, tgt);
    mma_kernel<<<dim3(Tn, 16), 256>>>(write_ids);
    light_kernel<<<dim3(Tn, 4), 256>>>(tgt, clw, out, write_ids);
    combine_kernel<<<1024, 256>>>(clw, out, write_ids);
    rescue_kernel<<<512, 256>>>(pred, tgt, clw, out, write_ids);
}